// round 10
// baseline (speedup 1.0000x reference)
#include <cuda_runtime.h>
#include <cstdint>
#include <math.h>

#define B_ 256
#define T_ 256
#define V_ 128
#define D_ 384
#define H_ 6
#define HS_ 64
#define L_ 6
#define FF_ 1536
#define N_ (B_*T_)   // 65536 tokens

// ---------------- scratch ---------------------------------------------------
__device__ float g_x [N_*D_];
__device__ float g_xn[N_*D_];
__device__ float g_q [N_*D_];
__device__ float g_k [N_*D_];
__device__ float g_v [N_*D_];
__device__ float g_o [N_*D_];
__device__ float g_h [N_*FF_];

// packed tf32-rounded weights
#define WQKV_OFF  0
#define WQKV_SZ   (L_*D_*3*D_)
#define WPROJ_OFF (WQKV_OFF + WQKV_SZ)
#define WPROJ_SZ  (L_*D_*D_)
#define W1_OFF    (WPROJ_OFF + WPROJ_SZ)
#define W1_SZ     (L_*D_*FF_)
#define W2_OFF    (W1_OFF + W1_SZ)
#define W2_SZ     (L_*FF_*D_)
#define WLM_OFF   (W2_OFF + W2_SZ)
#define WLM_SZ    (D_*V_)
#define WTOT      (WLM_OFF + WLM_SZ)
__device__ float g_w[WTOT];

// ---------------- tf32 helpers ---------------------------------------------
__device__ __forceinline__ uint32_t f2tf32(float f) {
    uint32_t r;
    asm("cvt.rna.tf32.f32 %0, %1;" : "=r"(r) : "f"(f));
    return r;
}
__device__ __forceinline__ float rndtf(float f) {
    return __uint_as_float(f2tf32(f));
}
__device__ __forceinline__ void mma_tf32(float c[4], const uint32_t a[4],
                                         const uint32_t b[2]) {
    asm volatile(
        "mma.sync.aligned.m16n8k8.row.col.f32.tf32.tf32.f32 "
        "{%0,%1,%2,%3}, {%4,%5,%6,%7}, {%8,%9}, {%0,%1,%2,%3};"
        : "+f"(c[0]), "+f"(c[1]), "+f"(c[2]), "+f"(c[3])
        : "r"(a[0]), "r"(a[1]), "r"(a[2]), "r"(a[3]),
          "r"(b[0]), "r"(b[1]));
}
__device__ __forceinline__ void cpasync16(uint32_t smem, const void* g) {
    asm volatile("cp.async.cg.shared.global [%0], [%1], 16;"
                 :: "r"(smem), "l"(g));
}
__device__ __forceinline__ uint32_t smaddr(const void* p) {
    return (uint32_t)__cvta_generic_to_shared(p);
}
// hi/lo split for tf32x3 (fp32-accurate tensor-core math)
__device__ __forceinline__ void split_tf(float x, uint32_t& hi, uint32_t& lo) {
    hi = f2tf32(x);
    lo = f2tf32(x - __uint_as_float(hi));
}

// ---------------- weight pre-pack -------------------------------------------
__global__ void pack_qkv_kernel(const float* __restrict__ Wq,
                                const float* __restrict__ Wk,
                                const float* __restrict__ Wv,
                                float* __restrict__ dst) {
    int i = blockIdx.x * 256 + threadIdx.x;          // over L*D*1152
    int n  = i % (3*D_);
    int ld = i / (3*D_);
    int d  = ld % D_, l = ld / D_;
    int qkv = n / D_;
    int rem = n - qkv*D_;
    int h = rem >> 6, hs = rem & 63;
    const float* W = (qkv == 0) ? Wq : (qkv == 1 ? Wk : Wv);
    float v = W[(((size_t)l*H_ + h)*D_ + d)*HS_ + hs];
    dst[i] = rndtf(v);
}

__global__ void round_copy_kernel(const float* __restrict__ src,
                                  float* __restrict__ dst) {
    int i = blockIdx.x * 256 + threadIdx.x;
    dst[i] = rndtf(src[i]);
}

// ---------------- embedding ------------------------------------------------
__global__ void embed_kernel(const int* __restrict__ idx,
                             const float* __restrict__ tok,
                             const float* __restrict__ pos,
                             float* __restrict__ x) {
    int i = blockIdx.x * 256 + threadIdx.x;
    int n = i / (D_/4);
    int dq = i % (D_/4);
    int t = n & (T_-1);
    int id = idx[n];
    float4 a = ((const float4*)tok)[id * (D_/4) + dq];
    float4 p = ((const float4*)pos)[t  * (D_/4) + dq];
    float4 r;
    r.x = a.x + p.x; r.y = a.y + p.y; r.z = a.z + p.z; r.w = a.w + p.w;
    ((float4*)x)[i] = r;
}

// ---------------- layernorm (warp per row, tf32-rounded output) -------------
__global__ void ln_kernel(const float* __restrict__ x,
                          const float* __restrict__ g,
                          const float* __restrict__ b,
                          float* __restrict__ out) {
    int row  = blockIdx.x * 8 + (threadIdx.x >> 5);
    int lane = threadIdx.x & 31;
    const float* xr = x + (size_t)row * D_;
    float vals[12];
    float s = 0.f, s2 = 0.f;
#pragma unroll
    for (int i = 0; i < 12; i++) {
        float t = xr[lane + 32*i];
        vals[i] = t; s += t; s2 += t*t;
    }
#pragma unroll
    for (int off = 16; off; off >>= 1) {
        s  += __shfl_xor_sync(0xffffffffu, s,  off);
        s2 += __shfl_xor_sync(0xffffffffu, s2, off);
    }
    float mean = s * (1.f/D_);
    float var  = s2 * (1.f/D_) - mean*mean;
    float rstd = rsqrtf(var + 1e-5f);
    float* orow = out + (size_t)row * D_;
#pragma unroll
    for (int i = 0; i < 12; i++) {
        int d = lane + 32*i;
        orow[d] = rndtf((vals[i] - mean) * rstd * g[d] + b[d]);
    }
}

// ---------------- pipelined TF32 GEMM, CTA 128x128 ---------------------------
#define A_STG (128*36)
#define B_STG (32*132)
#define GEMM_SMEM ((2*A_STG + 2*B_STG)*4)

__device__ __forceinline__ void fill_stage(float* As, float* Bs,
        const float* A, const float* Bp, int r0, int n0, int K, int ldb,
        int k0, int tid) {
#pragma unroll
    for (int i = 0; i < 4; i++) {
        int f = i*256 + tid;
        int m = f >> 3, c4 = f & 7;
        cpasync16(smaddr(As + m*36 + c4*4),
                  A + (size_t)(r0+m)*K + k0 + c4*4);
    }
#pragma unroll
    for (int i = 0; i < 4; i++) {
        int f = i*256 + tid;
        int kk = f >> 5, c4 = f & 31;
        cpasync16(smaddr(Bs + kk*132 + c4*4),
                  Bp + (size_t)(k0+kk)*ldb + n0 + c4*4);
    }
}

template<int MODE, bool QKV>
__global__ __launch_bounds__(256)
void gemm3(const float* __restrict__ A, const float* __restrict__ Bp,
           const float* __restrict__ bias, const float* __restrict__ res,
           float* __restrict__ C0, float* __restrict__ C1,
           float* __restrict__ C2, int K, int M) {
    extern __shared__ float sm[];
    float* As = sm;
    float* Bs = sm + 2*A_STG;

    const int tid  = threadIdx.x;
    const int lane = tid & 31, warp = tid >> 5;
    const int gid  = lane >> 2, tig = lane & 3;
    const int wm   = warp >> 2, wn = warp & 3;
    const int m0   = wm * 64,   n0w = wn * 32;
    const int r0   = blockIdx.y * 128;
    const int n0   = blockIdx.x * 128;

    float acc[4][4][4];
#pragma unroll
    for (int i = 0; i < 4; i++)
#pragma unroll
        for (int j = 0; j < 4; j++)
#pragma unroll
            for (int c = 0; c < 4; c++) acc[i][j][c] = 0.f;

    fill_stage(As, Bs, A, Bp, r0, n0, K, M, 0, tid);
    asm volatile("cp.async.commit_group;");

    int s = 0;
    for (int k0 = 0; k0 < K; k0 += 32) {
        if (k0 + 32 < K) {
            fill_stage(As + (1-s)*A_STG, Bs + (1-s)*B_STG,
                       A, Bp, r0, n0, K, M, k0 + 32, tid);
            asm volatile("cp.async.commit_group;");
            asm volatile("cp.async.wait_group 1;");
        } else {
            asm volatile("cp.async.wait_group 0;");
        }
        __syncthreads();

        const float* Ab = As + s*A_STG;
        const float* Bb = Bs + s*B_STG;
#pragma unroll
        for (int ks = 0; ks < 4; ks++) {
            const int kb = ks * 8;
            uint32_t af[4][4], bf[4][2];
#pragma unroll
            for (int mi = 0; mi < 4; mi++) {
                int rb = m0 + mi*16 + gid;
                af[mi][0] = __float_as_uint(Ab[(rb    )*36 + kb + tig    ]);
                af[mi][1] = __float_as_uint(Ab[(rb + 8)*36 + kb + tig    ]);
                af[mi][2] = __float_as_uint(Ab[(rb    )*36 + kb + tig + 4]);
                af[mi][3] = __float_as_uint(Ab[(rb + 8)*36 + kb + tig + 4]);
            }
#pragma unroll
            for (int ni = 0; ni < 4; ni++) {
                int cb = n0w + ni*8 + gid;
                bf[ni][0] = __float_as_uint(Bb[(kb + tig    )*132 + cb]);
                bf[ni][1] = __float_as_uint(Bb[(kb + tig + 4)*132 + cb]);
            }
#pragma unroll
            for (int mi = 0; mi < 4; mi++)
#pragma unroll
                for (int ni = 0; ni < 4; ni++)
                    mma_tf32(acc[mi][ni], af[mi], bf[ni]);
        }
        __syncthreads();
        s ^= 1;
    }

    if (QKV) {
        int qkv = blockIdx.x / 3;
        int cbase = blockIdx.x * 128 - qkv * 384;
        float* Cd = (qkv == 0) ? C0 : (qkv == 1 ? C1 : C2);
#pragma unroll
        for (int mi = 0; mi < 4; mi++) {
#pragma unroll
            for (int ni = 0; ni < 4; ni++) {
                int c = cbase + n0w + ni*8 + tig*2;
                int h = c >> 6, hs = c & 63;
#pragma unroll
                for (int rh = 0; rh < 2; rh++) {
                    int rr = r0 + m0 + mi*16 + gid + rh*8;
                    int bb = rr >> 8, t = rr & 255;
                    size_t oi = (((size_t)bb*H_ + h)*T_ + t)*64 + hs;
                    *(float2*)(Cd + oi) =
                        make_float2(acc[mi][ni][rh*2+0], acc[mi][ni][rh*2+1]);
                }
            }
        }
    } else {
#pragma unroll
        for (int mi = 0; mi < 4; mi++) {
#pragma unroll
            for (int ni = 0; ni < 4; ni++) {
                int col = n0 + n0w + ni*8 + tig*2;
                float2 bv = make_float2(0.f, 0.f);
                if (MODE >= 1) {
                    bv.x = bias[col];
                    bv.y = bias[col + 1];
                }
#pragma unroll
                for (int rh = 0; rh < 2; rh++) {
                    int rr = r0 + m0 + mi*16 + gid + rh*8;
                    float2 o;
                    o.x = acc[mi][ni][rh*2+0] + bv.x;
                    o.y = acc[mi][ni][rh*2+1] + bv.y;
                    if (MODE == 2) {
                        o.x = rndtf(fmaxf(o.x, 0.f));
                        o.y = rndtf(fmaxf(o.y, 0.f));
                    }
                    size_t ci = (size_t)rr*M + col;
                    if (MODE == 3) {
                        float2 rv = *(const float2*)(res + ci);
                        o.x += rv.x; o.y += rv.y;
                    }
                    *(float2*)(C0 + ci) = o;
                }
            }
        }
    }
}

// ---------------- MMA flash attention (tf32x3, fp32-accurate) ---------------
// 128 threads, 4 warps; Bq=Bkv=64; warp tile 16 rows x 64 cols.
// Smem: Qs[m][k] 64x68, Ks[d][s] 64x68 (B-layout for QK),
//       Vs[s][d] 64x68 (B-layout for PV), Ps[m][s] 64x68 (A for PV).
#define ATT_LD 68
#define ATT_TILE (64*ATT_LD)
#define ATT_SMEM (4*ATT_TILE*4)

__global__ __launch_bounds__(128)
void attn_mma(const float* __restrict__ q, const float* __restrict__ k,
              const float* __restrict__ v, float* __restrict__ o) {
    extern __shared__ float sm[];
    float* Qs = sm;
    float* Ks = sm + ATT_TILE;
    float* Vs = sm + 2*ATT_TILE;
    float* Ps = sm + 3*ATT_TILE;

    const int tid  = threadIdx.x;
    const int lane = tid & 31, warp = tid >> 5;
    const int gid  = lane >> 2, tig = lane & 3;
    const int m0w  = warp * 16;
    const int bh   = blockIdx.y;
    const int q0   = blockIdx.x * 64;
    const float* qb = q + (size_t)bh*T_*64;
    const float* kb = k + (size_t)bh*T_*64;
    const float* vb = v + (size_t)bh*T_*64;

    // load Q tile [r][d], raw fp32
#pragma unroll
    for (int i = 0; i < 8; i++) {
        int f = i*128 + tid;                 // 1024 float4
        int r = f >> 4, d4 = f & 15;
        *(float4*)&Qs[r*ATT_LD + d4*4] =
            *(const float4*)(qb + (q0+r)*64 + d4*4);
    }

    float mrow[2], lse[2];
    float oac[8][4];
    mrow[0] = mrow[1] = -1e30f;
    lse[0] = lse[1] = 0.f;
#pragma unroll
    for (int i = 0; i < 8; i++)
#pragma unroll
        for (int c = 0; c < 4; c++) oac[i][c] = 0.f;

    for (int s0 = 0; s0 <= q0; s0 += 64) {
        __syncthreads();
        // K transposed: Ks[d][s]; V straight: Vs[s][d]
#pragma unroll
        for (int i = 0; i < 8; i++) {
            int f = i*128 + tid;
            int r = f >> 4, d4 = f & 15;
            float4 kv4 = *(const float4*)(kb + (s0+r)*64 + d4*4);
            Ks[(d4*4+0)*ATT_LD + r] = kv4.x;
            Ks[(d4*4+1)*ATT_LD + r] = kv4.y;
            Ks[(d4*4+2)*ATT_LD + r] = kv4.z;
            Ks[(d4*4+3)*ATT_LD + r] = kv4.w;
            *(float4*)&Vs[r*ATT_LD + d4*4] =
                *(const float4*)(vb + (s0+r)*64 + d4*4);
        }
        __syncthreads();

        // ---- S = Q K^T (tf32x3) ----
        float sac[8][4];
#pragma unroll
        for (int i = 0; i < 8; i++)
#pragma unroll
            for (int c = 0; c < 4; c++) sac[i][c] = 0.f;

#pragma unroll
        for (int ks = 0; ks < 8; ks++) {
            const int kbd = ks * 8;
            uint32_t ah[4], al[4];
            split_tf(Qs[(m0w+gid  )*ATT_LD + kbd + tig    ], ah[0], al[0]);
            split_tf(Qs[(m0w+gid+8)*ATT_LD + kbd + tig    ], ah[1], al[1]);
            split_tf(Qs[(m0w+gid  )*ATT_LD + kbd + tig + 4], ah[2], al[2]);
            split_tf(Qs[(m0w+gid+8)*ATT_LD + kbd + tig + 4], ah[3], al[3]);
#pragma unroll
            for (int nb = 0; nb < 8; nb++) {
                int cb = nb*8 + gid;
                uint32_t bh2[2], bl2[2];
                split_tf(Ks[(kbd + tig    )*ATT_LD + cb], bh2[0], bl2[0]);
                split_tf(Ks[(kbd + tig + 4)*ATT_LD + cb], bh2[1], bl2[1]);
                mma_tf32(sac[nb], ah, bh2);
                mma_tf32(sac[nb], ah, bl2);
                mma_tf32(sac[nb], al, bh2);
            }
        }

        // ---- online softmax ----
        const bool diag = (s0 == q0);
        float tm0 = -1e30f, tm1 = -1e30f;
#pragma unroll
        for (int nb = 0; nb < 8; nb++) {
#pragma unroll
            for (int c = 0; c < 4; c++) {
                float val = sac[nb][c] * 0.125f;
                if (diag) {
                    int col = nb*8 + tig*2 + (c & 1);
                    int row = m0w + gid + ((c >> 1) ? 8 : 0);
                    if (col > row) val = -1e30f;
                }
                sac[nb][c] = val;
                if (c < 2) tm0 = fmaxf(tm0, val);
                else       tm1 = fmaxf(tm1, val);
            }
        }
        tm0 = fmaxf(tm0, __shfl_xor_sync(0xffffffffu, tm0, 1));
        tm0 = fmaxf(tm0, __shfl_xor_sync(0xffffffffu, tm0, 2));
        tm1 = fmaxf(tm1, __shfl_xor_sync(0xffffffffu, tm1, 1));
        tm1 = fmaxf(tm1, __shfl_xor_sync(0xffffffffu, tm1, 2));
        float nm0 = fmaxf(mrow[0], tm0), nm1 = fmaxf(mrow[1], tm1);
        float cr0 = __expf(mrow[0] - nm0), cr1 = __expf(mrow[1] - nm1);
        mrow[0] = nm0; mrow[1] = nm1;

        float rs0 = 0.f, rs1 = 0.f;
#pragma unroll
        for (int nb = 0; nb < 8; nb++) {
            float p0 = __expf(sac[nb][0] - nm0);
            float p1 = __expf(sac[nb][1] - nm0);
            float p2 = __expf(sac[nb][2] - nm1);
            float p3 = __expf(sac[nb][3] - nm1);
            rs0 += p0 + p1; rs1 += p2 + p3;
            *(float2*)&Ps[(m0w+gid  )*ATT_LD + nb*8 + tig*2] =
                make_float2(p0, p1);
            *(float2*)&Ps[(m0w+gid+8)*ATT_LD + nb*8 + tig*2] =
                make_float2(p2, p3);
        }
        rs0 += __shfl_xor_sync(0xffffffffu, rs0, 1);
        rs0 += __shfl_xor_sync(0xffffffffu, rs0, 2);
        rs1 += __shfl_xor_sync(0xffffffffu, rs1, 1);
        rs1 += __shfl_xor_sync(0xffffffffu, rs1, 2);
        lse[0] = lse[0]*cr0 + rs0;
        lse[1] = lse[1]*cr1 + rs1;
#pragma unroll
        for (int i = 0; i < 8; i++) {
            oac[i][0] *= cr0; oac[i][1] *= cr0;
            oac[i][2] *= cr1; oac[i][3] *= cr1;
        }
        __syncwarp();     // Ps rows m0w..m0w+15 written by this warp only

        // ---- O += P V (tf32x3) ----
#pragma unroll
        for (int ks = 0; ks < 8; ks++) {
            const int kbs = ks * 8;
            uint32_t ah[4], al[4];
            split_tf(Ps[(m0w+gid  )*ATT_LD + kbs + tig    ], ah[0], al[0]);
            split_tf(Ps[(m0w+gid+8)*ATT_LD + kbs + tig    ], ah[1], al[1]);
            split_tf(Ps[(m0w+gid  )*ATT_LD + kbs + tig + 4], ah[2], al[2]);
            split_tf(Ps[(m0w+gid+8)*ATT_LD + kbs + tig + 4], ah[3], al[3]);
#pragma unroll
            for (int nb = 0; nb < 8; nb++) {
                int cb = nb*8 + gid;
                uint32_t bh2[2], bl2[2];
                split_tf(Vs[(kbs + tig    )*ATT_LD + cb], bh2[0], bl2[0]);
                split_tf(Vs[(kbs + tig + 4)*ATT_LD + cb], bh2[1], bl2[1]);
                mma_tf32(oac[nb], ah, bh2);
                mma_tf32(oac[nb], ah, bl2);
                mma_tf32(oac[nb], al, bh2);
            }
        }
        __syncwarp();
    }

    // ---- epilogue: o[b][t][h*64+d], tf32-rounded ----
    const int bb = bh / H_, hh = bh % H_;
    const float inv0 = 1.f / lse[0], inv1 = 1.f / lse[1];
    const int t0 = q0 + m0w + gid;
#pragma unroll
    for (int nb = 0; nb < 8; nb++) {
        int col = hh*64 + nb*8 + tig*2;
        size_t oi0 = ((size_t)bb*T_ + t0    )*D_ + col;
        size_t oi1 = ((size_t)bb*T_ + t0 + 8)*D_ + col;
        *(float2*)(o + oi0) = make_float2(rndtf(oac[nb][0]*inv0),
                                          rndtf(oac[nb][1]*inv0));
        *(float2*)(o + oi1) = make_float2(rndtf(oac[nb][2]*inv1),
                                          rndtf(oac[nb][3]*inv1));
    }
}

// ---------------- launch ----------------------------------------------------
extern "C" void kernel_launch(void* const* d_in, const int* in_sizes, int n_in,
                              void* d_out, int out_size) {
    const int*   idx   = (const int*)  d_in[0];
    const float* tok   = (const float*)d_in[1];
    const float* pos   = (const float*)d_in[2];
    const float* Wq    = (const float*)d_in[3];
    const float* Wk    = (const float*)d_in[4];
    const float* Wv    = (const float*)d_in[5];
    const float* Wproj = (const float*)d_in[6];
    const float* bproj = (const float*)d_in[7];
    const float* ln1g  = (const float*)d_in[8];
    const float* ln1b  = (const float*)d_in[9];
    const float* ln2g  = (const float*)d_in[10];
    const float* ln2b  = (const float*)d_in[11];
    const float* W1    = (const float*)d_in[12];
    const float* b1    = (const float*)d_in[13];
    const float* W2    = (const float*)d_in[14];
    const float* b2    = (const float*)d_in[15];
    const float* lnfg  = (const float*)d_in[16];
    const float* lnfb  = (const float*)d_in[17];
    const float* Wlm   = (const float*)d_in[18];
    const float* blm   = (const float*)d_in[19];
    float* out = (float*)d_out;

    float *x, *xn, *q, *k, *v, *o, *h, *w;
    cudaGetSymbolAddress((void**)&x,  g_x);
    cudaGetSymbolAddress((void**)&xn, g_xn);
    cudaGetSymbolAddress((void**)&q,  g_q);
    cudaGetSymbolAddress((void**)&k,  g_k);
    cudaGetSymbolAddress((void**)&v,  g_v);
    cudaGetSymbolAddress((void**)&o,  g_o);
    cudaGetSymbolAddress((void**)&h,  g_h);
    cudaGetSymbolAddress((void**)&w,  g_w);

    cudaFuncSetAttribute(attn_mma,
        cudaFuncAttributeMaxDynamicSharedMemorySize, ATT_SMEM);
    cudaFuncSetAttribute(gemm3<0,true>,
        cudaFuncAttributeMaxDynamicSharedMemorySize, GEMM_SMEM);
    cudaFuncSetAttribute(gemm3<1,false>,
        cudaFuncAttributeMaxDynamicSharedMemorySize, GEMM_SMEM);
    cudaFuncSetAttribute(gemm3<2,false>,
        cudaFuncAttributeMaxDynamicSharedMemorySize, GEMM_SMEM);
    cudaFuncSetAttribute(gemm3<3,false>,
        cudaFuncAttributeMaxDynamicSharedMemorySize, GEMM_SMEM);

    // weight pre-pack (tf32-rounded)
    pack_qkv_kernel<<<WQKV_SZ/256, 256>>>(Wq, Wk, Wv, w + WQKV_OFF);
    round_copy_kernel<<<WPROJ_SZ/256, 256>>>(Wproj, w + WPROJ_OFF);
    round_copy_kernel<<<W1_SZ/256, 256>>>(W1, w + W1_OFF);
    round_copy_kernel<<<W2_SZ/256, 256>>>(W2, w + W2_OFF);
    round_copy_kernel<<<WLM_SZ/256, 256>>>(Wlm, w + WLM_OFF);

    embed_kernel<<<(N_*D_/4)/256, 256>>>(idx, tok, pos, x);

    for (int l = 0; l < L_; l++) {
        ln_kernel<<<N_/8, 256>>>(x, ln1g + l*D_, ln1b + l*D_, xn);

        gemm3<0,true><<<dim3(9, N_/128), 256, GEMM_SMEM>>>(
            xn, w + WQKV_OFF + (size_t)l*D_*3*D_, nullptr, nullptr,
            q, k, v, D_, 3*D_);

        attn_mma<<<dim3(T_/64, B_*H_), 128, ATT_SMEM>>>(q, k, v, o);

        gemm3<3,false><<<dim3(3, N_/128), 256, GEMM_SMEM>>>(
            o, w + WPROJ_OFF + (size_t)l*D_*D_, bproj + l*D_, x,
            x, nullptr, nullptr, D_, D_);

        ln_kernel<<<N_/8, 256>>>(x, ln2g + l*D_, ln2b + l*D_, xn);

        gemm3<2,false><<<dim3(12, N_/128), 256, GEMM_SMEM>>>(
            xn, w + W1_OFF + (size_t)l*D_*FF_, b1 + l*FF_, nullptr,
            h, nullptr, nullptr, D_, FF_);

        gemm3<3,false><<<dim3(3, N_/128), 256, GEMM_SMEM>>>(
            h, w + W2_OFF + (size_t)l*FF_*D_, b2 + l*D_, x,
            x, nullptr, nullptr, FF_, D_);
    }

    ln_kernel<<<N_/8, 256>>>(x, lnfg, lnfb, xn);
    gemm3<1,false><<<dim3(1, N_/128), 256, GEMM_SMEM>>>(
        xn, w + WLM_OFF, blm, nullptr, out, nullptr, nullptr, D_, V_);
}

// round 12
// speedup vs baseline: 1.4463x; 1.4463x over previous
#include <cuda_runtime.h>
#include <cuda_fp16.h>
#include <cstdint>
#include <math.h>

#define B_ 256
#define T_ 256
#define V_ 128
#define D_ 384
#define H_ 6
#define HS_ 64
#define L_ 6
#define FF_ 1536
#define N_ (B_*T_)   // 65536 tokens

// ---------------- scratch ---------------------------------------------------
__device__ float  g_x [N_*D_];
__device__ __half g_xn[N_*D_];
__device__ float  g_q [N_*D_];
__device__ float  g_k [N_*D_];
__device__ float  g_v [N_*D_];
__device__ __half g_o [N_*D_];
__device__ __half g_h [N_*FF_];

// packed fp16, TRANSPOSED weights (Bt[n][k], K contiguous)
#define WQKV_OFF  0
#define WQKV_SZ   (L_*D_*3*D_)
#define WPROJ_OFF (WQKV_OFF + WQKV_SZ)
#define WPROJ_SZ  (L_*D_*D_)
#define W1_OFF    (WPROJ_OFF + WPROJ_SZ)
#define W1_SZ     (L_*D_*FF_)
#define W2_OFF    (W1_OFF + W1_SZ)
#define W2_SZ     (L_*FF_*D_)
#define WLM_OFF   (W2_OFF + W2_SZ)
#define WLM_SZ    (D_*V_)
#define WTOT      (WLM_OFF + WLM_SZ)
__device__ __half g_w[WTOT];

// ---------------- helpers ---------------------------------------------------
__device__ __forceinline__ uint32_t f2tf32(float f) {
    uint32_t r;
    asm("cvt.rna.tf32.f32 %0, %1;" : "=r"(r) : "f"(f));
    return r;
}
__device__ __forceinline__ void mma_tf32(float c[4], const uint32_t a[4],
                                         const uint32_t b[2]) {
    asm volatile(
        "mma.sync.aligned.m16n8k8.row.col.f32.tf32.tf32.f32 "
        "{%0,%1,%2,%3}, {%4,%5,%6,%7}, {%8,%9}, {%0,%1,%2,%3};"
        : "+f"(c[0]), "+f"(c[1]), "+f"(c[2]), "+f"(c[3])
        : "r"(a[0]), "r"(a[1]), "r"(a[2]), "r"(a[3]),
          "r"(b[0]), "r"(b[1]));
}
__device__ __forceinline__ void mma_f16(float c[4], const uint32_t a[4],
                                        const uint32_t b[2]) {
    asm volatile(
        "mma.sync.aligned.m16n8k16.row.col.f32.f16.f16.f32 "
        "{%0,%1,%2,%3}, {%4,%5,%6,%7}, {%8,%9}, {%0,%1,%2,%3};"
        : "+f"(c[0]), "+f"(c[1]), "+f"(c[2]), "+f"(c[3])
        : "r"(a[0]), "r"(a[1]), "r"(a[2]), "r"(a[3]),
          "r"(b[0]), "r"(b[1]));
}
__device__ __forceinline__ void cpasync16(uint32_t smem, const void* g) {
    asm volatile("cp.async.cg.shared.global [%0], [%1], 16;"
                 :: "r"(smem), "l"(g));
}
__device__ __forceinline__ uint32_t smaddr(const void* p) {
    return (uint32_t)__cvta_generic_to_shared(p);
}
__device__ __forceinline__ void split_tf(float x, uint32_t& hi, uint32_t& lo) {
    hi = f2tf32(x);
    lo = f2tf32(x - __uint_as_float(hi));
}

// ---------------- weight pre-pack (tiled transpose + fp16) ------------------
__global__ void transpose_h_kernel(const float* __restrict__ src,
                                   __half* __restrict__ dst,
                                   int K, int M) {
    __shared__ float t[32][33];
    int l  = blockIdx.z;
    int kb = blockIdx.x * 32, mb = blockIdx.y * 32;
    int x = threadIdx.x, y = threadIdx.y;
    const float* s = src + (size_t)l * K * M;
    __half* d = dst + (size_t)l * M * K;
#pragma unroll
    for (int i = 0; i < 32; i += 8)
        t[y + i][x] = s[(size_t)(kb + y + i) * M + mb + x];
    __syncthreads();
#pragma unroll
    for (int i = 0; i < 32; i += 8)
        d[(size_t)(mb + y + i) * K + kb + x] = __float2half_rn(t[x][y + i]);
}

// QKV: W[l][h][d][hs] -> dst row n = qkv*384 + h*64 + hs, col k = d
__global__ void pack_qkv_h_kernel(const float* __restrict__ W,
                                  __half* __restrict__ dst, int qkv) {
    __shared__ float t[32][33];
    int z = blockIdx.z;
    int l = z / H_, h = z - l * H_;
    int kb = blockIdx.x * 32, mb = blockIdx.y * 32;
    int x = threadIdx.x, y = threadIdx.y;
    const float* s = W + (size_t)(l * H_ + h) * D_ * HS_;
    __half* d = dst + ((size_t)l * (3*D_) + qkv * D_ + h * HS_) * D_;
#pragma unroll
    for (int i = 0; i < 32; i += 8)
        t[y + i][x] = s[(size_t)(kb + y + i) * HS_ + mb + x];
    __syncthreads();
#pragma unroll
    for (int i = 0; i < 32; i += 8)
        d[(size_t)(mb + y + i) * D_ + kb + x] = __float2half_rn(t[x][y + i]);
}

// ---------------- embedding ------------------------------------------------
__global__ void embed_kernel(const int* __restrict__ idx,
                             const float* __restrict__ tok,
                             const float* __restrict__ pos,
                             float* __restrict__ x) {
    int i = blockIdx.x * 256 + threadIdx.x;
    int n = i / (D_/4);
    int dq = i % (D_/4);
    int t = n & (T_-1);
    int id = idx[n];
    float4 a = ((const float4*)tok)[id * (D_/4) + dq];
    float4 p = ((const float4*)pos)[t  * (D_/4) + dq];
    float4 r;
    r.x = a.x + p.x; r.y = a.y + p.y; r.z = a.z + p.z; r.w = a.w + p.w;
    ((float4*)x)[i] = r;
}

// ---------------- layernorm (warp per row, fp16 output) ---------------------
__global__ void ln_kernel(const float* __restrict__ x,
                          const float* __restrict__ g,
                          const float* __restrict__ b,
                          __half* __restrict__ out) {
    int row  = blockIdx.x * 8 + (threadIdx.x >> 5);
    int lane = threadIdx.x & 31;
    const float* xr = x + (size_t)row * D_;
    float vals[12];
    float s = 0.f, s2 = 0.f;
#pragma unroll
    for (int i = 0; i < 12; i++) {
        float t = xr[lane + 32*i];
        vals[i] = t; s += t; s2 += t*t;
    }
#pragma unroll
    for (int off = 16; off; off >>= 1) {
        s  += __shfl_xor_sync(0xffffffffu, s,  off);
        s2 += __shfl_xor_sync(0xffffffffu, s2, off);
    }
    float mean = s * (1.f/D_);
    float var  = s2 * (1.f/D_) - mean*mean;
    float rstd = rsqrtf(var + 1e-5f);
    __half* orow = out + (size_t)row * D_;
#pragma unroll
    for (int i = 0; i < 12; i++) {
        int d = lane + 32*i;
        orow[d] = __float2half_rn((vals[i] - mean) * rstd * g[d] + b[d]);
    }
}

// ---------------- fp16 tensor-core GEMM, CTA 128x128 -------------------------
// C[N x M] = A[N x K] @ Bt[M x K]^T, A/Bt fp16, fp32 accumulate.
// 8 warps, warp tile 64x32 (2x4 grid). BK=32 halves, 2-stage cp.async.
// Smem: half[128][40] per tile (20 words/row, conflict-free frag LDS).
// MODE: 0 none(QKV scatter, fp32 out), 1 +bias(fp32), 2 relu+bias(fp16 out),
//       3 +bias+residual(fp32)
#define TILE_H (128*40)     // halves per tile
#define GEMM_SMEM (4*TILE_H*2)

__device__ __forceinline__ void fill_h(__half* As, __half* Bs,
        const __half* A, const __half* Bt, int r0, int n0, int K,
        int k0, int tid) {
#pragma unroll
    for (int i = 0; i < 2; i++) {          // 512 chunks of 16B / 256 thr
        int f = i*256 + tid;
        int m = f >> 2, c8 = f & 3;
        cpasync16(smaddr(As + m*40 + c8*8),
                  A + (size_t)(r0+m)*K + k0 + c8*8);
    }
#pragma unroll
    for (int i = 0; i < 2; i++) {
        int f = i*256 + tid;
        int m = f >> 2, c8 = f & 3;
        cpasync16(smaddr(Bs + m*40 + c8*8),
                  Bt + (size_t)(n0+m)*K + k0 + c8*8);
    }
}

template<int MODE, bool QKV>
__global__ __launch_bounds__(256)
void gemm6(const __half* __restrict__ A, const __half* __restrict__ Bt,
           const float* __restrict__ bias, const float* __restrict__ res,
           void* __restrict__ C0v, float* __restrict__ C1,
           float* __restrict__ C2, int K, int M) {
    extern __shared__ __half smh[];
    __half* As = smh;                      // 2 stages A, then 2 stages B
    __half* Bs = smh + 2*TILE_H;

    const int tid  = threadIdx.x;
    const int lane = tid & 31, warp = tid >> 5;
    const int gid  = lane >> 2, tig = lane & 3;
    const int wm   = warp >> 2, wn = warp & 3;
    const int m0   = wm * 64,   n0w = wn * 32;
    const int r0   = blockIdx.y * 128;
    const int n0   = blockIdx.x * 128;

    float acc[4][4][4];
#pragma unroll
    for (int i = 0; i < 4; i++)
#pragma unroll
        for (int j = 0; j < 4; j++)
#pragma unroll
            for (int c = 0; c < 4; c++) acc[i][j][c] = 0.f;

    fill_h(As, Bs, A, Bt, r0, n0, K, 0, tid);
    asm volatile("cp.async.commit_group;");

    int s = 0;
    for (int k0 = 0; k0 < K; k0 += 32) {
        if (k0 + 32 < K) {
            fill_h(As + (1-s)*TILE_H, Bs + (1-s)*TILE_H,
                   A, Bt, r0, n0, K, k0 + 32, tid);
            asm volatile("cp.async.commit_group;");
            asm volatile("cp.async.wait_group 1;");
        } else {
            asm volatile("cp.async.wait_group 0;");
        }
        __syncthreads();

        const uint32_t* Ab = (const uint32_t*)(As + s*TILE_H);
        const uint32_t* Bb = (const uint32_t*)(Bs + s*TILE_H);
#pragma unroll
        for (int ks = 0; ks < 2; ks++) {           // two k16 steps
            const int kw = ks * 8;                 // word offset
            uint32_t af[4][4], bf[4][2];
#pragma unroll
            for (int mi = 0; mi < 4; mi++) {
                int rb = m0 + mi*16 + gid;
                af[mi][0] = Ab[(rb    )*20 + kw + tig    ];
                af[mi][1] = Ab[(rb + 8)*20 + kw + tig    ];
                af[mi][2] = Ab[(rb    )*20 + kw + tig + 4];
                af[mi][3] = Ab[(rb + 8)*20 + kw + tig + 4];
            }
#pragma unroll
            for (int ni = 0; ni < 4; ni++) {
                int cb = n0w + ni*8 + gid;
                bf[ni][0] = Bb[cb*20 + kw + tig    ];
                bf[ni][1] = Bb[cb*20 + kw + tig + 4];
            }
#pragma unroll
            for (int mi = 0; mi < 4; mi++)
#pragma unroll
                for (int ni = 0; ni < 4; ni++)
                    mma_f16(acc[mi][ni], af[mi], bf[ni]);
        }
        __syncthreads();
        s ^= 1;
    }

    // ---- epilogue ----
    if (QKV) {
        float* C0 = (float*)C0v;
        int qkv = blockIdx.x / 3;
        int cbase = blockIdx.x * 128 - qkv * 384;
        float* Cd = (qkv == 0) ? C0 : (qkv == 1 ? C1 : C2);
#pragma unroll
        for (int mi = 0; mi < 4; mi++) {
#pragma unroll
            for (int ni = 0; ni < 4; ni++) {
                int c = cbase + n0w + ni*8 + tig*2;
                int h = c >> 6, hs = c & 63;
#pragma unroll
                for (int rh = 0; rh < 2; rh++) {
                    int rr = r0 + m0 + mi*16 + gid + rh*8;
                    int bb = rr >> 8, t = rr & 255;
                    size_t oi = (((size_t)bb*H_ + h)*T_ + t)*64 + hs;
                    *(float2*)(Cd + oi) =
                        make_float2(acc[mi][ni][rh*2+0], acc[mi][ni][rh*2+1]);
                }
            }
        }
    } else {
#pragma unroll
        for (int mi = 0; mi < 4; mi++) {
#pragma unroll
            for (int ni = 0; ni < 4; ni++) {
                int col = n0 + n0w + ni*8 + tig*2;
                float2 bv = make_float2(0.f, 0.f);
                if (MODE >= 1) {
                    bv.x = bias[col];
                    bv.y = bias[col + 1];
                }
#pragma unroll
                for (int rh = 0; rh < 2; rh++) {
                    int rr = r0 + m0 + mi*16 + gid + rh*8;
                    float2 o;
                    o.x = acc[mi][ni][rh*2+0] + bv.x;
                    o.y = acc[mi][ni][rh*2+1] + bv.y;
                    size_t ci = (size_t)rr*M + col;
                    if (MODE == 2) {
                        o.x = fmaxf(o.x, 0.f); o.y = fmaxf(o.y, 0.f);
                        *(__half2*)((__half*)C0v + ci) =
                            __floats2half2_rn(o.x, o.y);
                    } else {
                        if (MODE == 3) {
                            float2 rv = *(const float2*)(res + ci);
                            o.x += rv.x; o.y += rv.y;
                        }
                        *(float2*)((float*)C0v + ci) = o;
                    }
                }
            }
        }
    }
}

// ---------------- MMA flash attention (tf32x3, fp32-accurate) ---------------
// fp32 q,k,v in; fp16 o out ([B,T,D] concat)
#define ATT_LD 68
#define ATT_TILE (64*ATT_LD)
#define ATT_SMEM (4*ATT_TILE*4)

__global__ __launch_bounds__(128)
void attn_mma(const float* __restrict__ q, const float* __restrict__ k,
              const float* __restrict__ v, __half* __restrict__ o) {
    extern __shared__ float sm[];
    float* Qs = sm;
    float* Ks = sm + ATT_TILE;
    float* Vs = sm + 2*ATT_TILE;
    float* Ps = sm + 3*ATT_TILE;

    const int tid  = threadIdx.x;
    const int lane = tid & 31, warp = tid >> 5;
    const int gid  = lane >> 2, tig = lane & 3;
    const int m0w  = warp * 16;
    const int bh   = blockIdx.y;
    const int q0   = blockIdx.x * 64;
    const float* qb = q + (size_t)bh*T_*64;
    const float* kb = k + (size_t)bh*T_*64;
    const float* vb = v + (size_t)bh*T_*64;

#pragma unroll
    for (int i = 0; i < 8; i++) {
        int f = i*128 + tid;
        int r = f >> 4, d4 = f & 15;
        *(float4*)&Qs[r*ATT_LD + d4*4] =
            *(const float4*)(qb + (q0+r)*64 + d4*4);
    }

    float mrow[2], lse[2];
    float oac[8][4];
    mrow[0] = mrow[1] = -1e30f;
    lse[0] = lse[1] = 0.f;
#pragma unroll
    for (int i = 0; i < 8; i++)
#pragma unroll
        for (int c = 0; c < 4; c++) oac[i][c] = 0.f;

    for (int s0 = 0; s0 <= q0; s0 += 64) {
        __syncthreads();
#pragma unroll
        for (int i = 0; i < 8; i++) {
            int f = i*128 + tid;
            int r = f >> 4, d4 = f & 15;
            float4 kv4 = *(const float4*)(kb + (s0+r)*64 + d4*4);
            Ks[(d4*4+0)*ATT_LD + r] = kv4.x;
            Ks[(d4*4+1)*ATT_LD + r] = kv4.y;
            Ks[(d4*4+2)*ATT_LD + r] = kv4.z;
            Ks[(d4*4+3)*ATT_LD + r] = kv4.w;
            *(float4*)&Vs[r*ATT_LD + d4*4] =
                *(const float4*)(vb + (s0+r)*64 + d4*4);
        }
        __syncthreads();

        float sac[8][4];
#pragma unroll
        for (int i = 0; i < 8; i++)
#pragma unroll
            for (int c = 0; c < 4; c++) sac[i][c] = 0.f;

#pragma unroll
        for (int ks = 0; ks < 8; ks++) {
            const int kbd = ks * 8;
            uint32_t ah[4], al[4];
            split_tf(Qs[(m0w+gid  )*ATT_LD + kbd + tig    ], ah[0], al[0]);
            split_tf(Qs[(m0w+gid+8)*ATT_LD + kbd + tig    ], ah[1], al[1]);
            split_tf(Qs[(m0w+gid  )*ATT_LD + kbd + tig + 4], ah[2], al[2]);
            split_tf(Qs[(m0w+gid+8)*ATT_LD + kbd + tig + 4], ah[3], al[3]);
#pragma unroll
            for (int nb = 0; nb < 8; nb++) {
                int cb = nb*8 + gid;
                uint32_t bh2[2], bl2[2];
                split_tf(Ks[(kbd + tig    )*ATT_LD + cb], bh2[0], bl2[0]);
                split_tf(Ks[(kbd + tig + 4)*ATT_LD + cb], bh2[1], bl2[1]);
                mma_tf32(sac[nb], ah, bh2);
                mma_tf32(sac[nb], ah, bl2);
                mma_tf32(sac[nb], al, bh2);
            }
        }

        const bool diag = (s0 == q0);
        float tm0 = -1e30f, tm1 = -1e30f;
#pragma unroll
        for (int nb = 0; nb < 8; nb++) {
#pragma unroll
            for (int c = 0; c < 4; c++) {
                float val = sac[nb][c] * 0.125f;
                if (diag) {
                    int col = nb*8 + tig*2 + (c & 1);
                    int row = m0w + gid + ((c >> 1) ? 8 : 0);
                    if (col > row) val = -1e30f;
                }
                sac[nb][c] = val;
                if (c < 2) tm0 = fmaxf(tm0, val);
                else       tm1 = fmaxf(tm1, val);
            }
        }
        tm0 = fmaxf(tm0, __shfl_xor_sync(0xffffffffu, tm0, 1));
        tm0 = fmaxf(tm0, __shfl_xor_sync(0xffffffffu, tm0, 2));
        tm1 = fmaxf(tm1, __shfl_xor_sync(0xffffffffu, tm1, 1));
        tm1 = fmaxf(tm1, __shfl_xor_sync(0xffffffffu, tm1, 2));
        float nm0 = fmaxf(mrow[0], tm0), nm1 = fmaxf(mrow[1], tm1);
        float cr0 = __expf(mrow[0] - nm0), cr1 = __expf(mrow[1] - nm1);
        mrow[0] = nm0; mrow[1] = nm1;

        float rs0 = 0.f, rs1 = 0.f;
#pragma unroll
        for (int nb = 0; nb < 8; nb++) {
            float p0 = __expf(sac[nb][0] - nm0);
            float p1 = __expf(sac[nb][1] - nm0);
            float p2 = __expf(sac[nb][2] - nm1);
            float p3 = __expf(sac[nb][3] - nm1);
            rs0 += p0 + p1; rs1 += p2 + p3;
            *(float2*)&Ps[(m0w+gid  )*ATT_LD + nb*8 + tig*2] =
                make_float2(p0, p1);
            *(float2*)&Ps[(m0w+gid+8)*ATT_LD + nb*8 + tig*2] =
                make_float2(p2, p3);
        }
        rs0 += __shfl_xor_sync(0xffffffffu, rs0, 1);
        rs0 += __shfl_xor_sync(0xffffffffu, rs0, 2);
        rs1 += __shfl_xor_sync(0xffffffffu, rs1, 1);
        rs1 += __shfl_xor_sync(0xffffffffu, rs1, 2);
        lse[0] = lse[0]*cr0 + rs0;
        lse[1] = lse[1]*cr1 + rs1;
#pragma unroll
        for (int i = 0; i < 8; i++) {
            oac[i][0] *= cr0; oac[i][1] *= cr0;
            oac[i][2] *= cr1; oac[i][3] *= cr1;
        }
        __syncwarp();

#pragma unroll
        for (int ks = 0; ks < 8; ks++) {
            const int kbs = ks * 8;
            uint32_t ah[4], al[4];
            split_tf(Ps[(m0w+gid  )*ATT_LD + kbs + tig    ], ah[0], al[0]);
            split_tf(Ps[(m0w+gid+8)*ATT_LD + kbs + tig    ], ah[1], al[1]);
            split_tf(Ps[(m0w+gid  )*ATT_LD + kbs + tig + 4], ah[2], al[2]);
            split_tf(Ps[(m0w+gid+8)*ATT_LD + kbs + tig + 4], ah[3], al[3]);
#pragma unroll
            for (int nb = 0; nb < 8; nb++) {
                int cb = nb*8 + gid;
                uint32_t bh2[2], bl2[2];
                split_tf(Vs[(kbs + tig    )*ATT_LD + cb], bh2[0], bl2[0]);
                split_tf(Vs[(kbs + tig + 4)*ATT_LD + cb], bh2[1], bl2[1]);
                mma_tf32(oac[nb], ah, bh2);
                mma_tf32(oac[nb], ah, bl2);
                mma_tf32(oac[nb], al, bh2);
            }
        }
        __syncwarp();
    }

    const int bb = bh / H_, hh = bh % H_;
    const float inv0 = 1.f / lse[0], inv1 = 1.f / lse[1];
    const int t0 = q0 + m0w + gid;
#pragma unroll
    for (int nb = 0; nb < 8; nb++) {
        int col = hh*64 + nb*8 + tig*2;
        size_t oi0 = ((size_t)bb*T_ + t0    )*D_ + col;
        size_t oi1 = ((size_t)bb*T_ + t0 + 8)*D_ + col;
        *(__half2*)(o + oi0) = __floats2half2_rn(oac[nb][0]*inv0,
                                                 oac[nb][1]*inv0);
        *(__half2*)(o + oi1) = __floats2half2_rn(oac[nb][2]*inv1,
                                                 oac[nb][3]*inv1);
    }
}

// ---------------- launch ----------------------------------------------------
extern "C" void kernel_launch(void* const* d_in, const int* in_sizes, int n_in,
                              void* d_out, int out_size) {
    const int*   idx   = (const int*)  d_in[0];
    const float* tok   = (const float*)d_in[1];
    const float* pos   = (const float*)d_in[2];
    const float* Wq    = (const float*)d_in[3];
    const float* Wk    = (const float*)d_in[4];
    const float* Wv    = (const float*)d_in[5];
    const float* Wproj = (const float*)d_in[6];
    const float* bproj = (const float*)d_in[7];
    const float* ln1g  = (const float*)d_in[8];
    const float* ln1b  = (const float*)d_in[9];
    const float* ln2g  = (const float*)d_in[10];
    const float* ln2b  = (const float*)d_in[11];
    const float* W1    = (const float*)d_in[12];
    const float* b1    = (const float*)d_in[13];
    const float* W2    = (const float*)d_in[14];
    const float* b2    = (const float*)d_in[15];
    const float* lnfg  = (const float*)d_in[16];
    const float* lnfb  = (const float*)d_in[17];
    const float* Wlm   = (const float*)d_in[18];
    const float* blm   = (const float*)d_in[19];
    float* out = (float*)d_out;

    float *x, *q, *k, *v;
    __half *xn, *o, *h, *w;
    cudaGetSymbolAddress((void**)&x,  g_x);
    cudaGetSymbolAddress((void**)&xn, g_xn);
    cudaGetSymbolAddress((void**)&q,  g_q);
    cudaGetSymbolAddress((void**)&k,  g_k);
    cudaGetSymbolAddress((void**)&v,  g_v);
    cudaGetSymbolAddress((void**)&o,  g_o);
    cudaGetSymbolAddress((void**)&h,  g_h);
    cudaGetSymbolAddress((void**)&w,  g_w);

    cudaFuncSetAttribute(attn_mma,
        cudaFuncAttributeMaxDynamicSharedMemorySize, ATT_SMEM);
    cudaFuncSetAttribute(gemm6<0,true>,
        cudaFuncAttributeMaxDynamicSharedMemorySize, GEMM_SMEM);
    cudaFuncSetAttribute(gemm6<1,false>,
        cudaFuncAttributeMaxDynamicSharedMemorySize, GEMM_SMEM);
    cudaFuncSetAttribute(gemm6<2,false>,
        cudaFuncAttributeMaxDynamicSharedMemorySize, GEMM_SMEM);
    cudaFuncSetAttribute(gemm6<3,false>,
        cudaFuncAttributeMaxDynamicSharedMemorySize, GEMM_SMEM);

    // weight pre-pack (transposed, fp16)
    {
        dim3 blk(32, 8);
        pack_qkv_h_kernel<<<dim3(D_/32, HS_/32, L_*H_), blk>>>(Wq, w+WQKV_OFF, 0);
        pack_qkv_h_kernel<<<dim3(D_/32, HS_/32, L_*H_), blk>>>(Wk, w+WQKV_OFF, 1);
        pack_qkv_h_kernel<<<dim3(D_/32, HS_/32, L_*H_), blk>>>(Wv, w+WQKV_OFF, 2);
        transpose_h_kernel<<<dim3(D_/32,  D_/32,  L_), blk>>>(Wproj, w+WPROJ_OFF, D_,  D_);
        transpose_h_kernel<<<dim3(D_/32,  FF_/32, L_), blk>>>(W1,    w+W1_OFF,    D_,  FF_);
        transpose_h_kernel<<<dim3(FF_/32, D_/32,  L_), blk>>>(W2,    w+W2_OFF,    FF_, D_);
        transpose_h_kernel<<<dim3(D_/32,  V_/32,  1 ), blk>>>(Wlm,   w+WLM_OFF,   D_,  V_);
    }

    embed_kernel<<<(N_*D_/4)/256, 256>>>(idx, tok, pos, x);

    for (int l = 0; l < L_; l++) {
        ln_kernel<<<N_/8, 256>>>(x, ln1g + l*D_, ln1b + l*D_, xn);

        gemm6<0,true><<<dim3(9, N_/128), 256, GEMM_SMEM>>>(
            xn, w + WQKV_OFF + (size_t)l*D_*3*D_, nullptr, nullptr,
            q, k, v, D_, 3*D_);

        attn_mma<<<dim3(T_/64, B_*H_), 128, ATT_SMEM>>>(q, k, v, o);

        gemm6<3,false><<<dim3(3, N_/128), 256, GEMM_SMEM>>>(
            o, w + WPROJ_OFF + (size_t)l*D_*D_, bproj + l*D_, x,
            x, nullptr, nullptr, D_, D_);

        ln_kernel<<<N_/8, 256>>>(x, ln2g + l*D_, ln2b + l*D_, xn);

        gemm6<2,false><<<dim3(12, N_/128), 256, GEMM_SMEM>>>(
            xn, w + W1_OFF + (size_t)l*D_*FF_, b1 + l*FF_, nullptr,
            h, nullptr, nullptr, D_, FF_);

        gemm6<3,false><<<dim3(3, N_/128), 256, GEMM_SMEM>>>(
            h, w + W2_OFF + (size_t)l*FF_*D_, b2 + l*D_, x,
            x, nullptr, nullptr, FF_, D_);
    }

    ln_kernel<<<N_/8, 256>>>(x, lnfg, lnfb, xn);
    gemm6<1,false><<<dim3(1, N_/128), 256, GEMM_SMEM>>>(
        xn, w + WLM_OFF, blm, nullptr, out, nullptr, nullptr, D_, V_);
}

// round 13
// speedup vs baseline: 1.8736x; 1.2954x over previous
#include <cuda_runtime.h>
#include <cuda_fp16.h>
#include <cstdint>
#include <math.h>

#define B_ 256
#define T_ 256
#define V_ 128
#define D_ 384
#define H_ 6
#define HS_ 64
#define L_ 6
#define FF_ 1536
#define N_ (B_*T_)   // 65536 tokens

// ---------------- scratch ---------------------------------------------------
__device__ float  g_x [N_*D_];
__device__ __half g_xn[N_*D_];
__device__ __half g_q [N_*D_];
__device__ __half g_k [N_*D_];
__device__ __half g_v [N_*D_];
__device__ __half g_o [N_*D_];
__device__ __half g_h [N_*FF_];

// packed fp16, TRANSPOSED weights (Bt[n][k], K contiguous)
#define WQKV_OFF  0
#define WQKV_SZ   (L_*D_*3*D_)
#define WPROJ_OFF (WQKV_OFF + WQKV_SZ)
#define WPROJ_SZ  (L_*D_*D_)
#define W1_OFF    (WPROJ_OFF + WPROJ_SZ)
#define W1_SZ     (L_*D_*FF_)
#define W2_OFF    (W1_OFF + W1_SZ)
#define W2_SZ     (L_*FF_*D_)
#define WLM_OFF   (W2_OFF + W2_SZ)
#define WLM_SZ    (D_*V_)
#define WTOT      (WLM_OFF + WLM_SZ)
__device__ __half g_w[WTOT];

// ---------------- helpers ---------------------------------------------------
__device__ __forceinline__ void mma_f16(float c[4], const uint32_t a[4],
                                        const uint32_t b[2]) {
    asm volatile(
        "mma.sync.aligned.m16n8k16.row.col.f32.f16.f16.f32 "
        "{%0,%1,%2,%3}, {%4,%5,%6,%7}, {%8,%9}, {%0,%1,%2,%3};"
        : "+f"(c[0]), "+f"(c[1]), "+f"(c[2]), "+f"(c[3])
        : "r"(a[0]), "r"(a[1]), "r"(a[2]), "r"(a[3]),
          "r"(b[0]), "r"(b[1]));
}
__device__ __forceinline__ void ldsm_x4(uint32_t& r0, uint32_t& r1,
                                        uint32_t& r2, uint32_t& r3,
                                        uint32_t addr) {
    asm volatile(
        "ldmatrix.sync.aligned.m8n8.x4.shared.b16 {%0,%1,%2,%3}, [%4];"
        : "=r"(r0), "=r"(r1), "=r"(r2), "=r"(r3) : "r"(addr));
}
__device__ __forceinline__ void cpasync16(uint32_t smem, const void* g) {
    asm volatile("cp.async.cg.shared.global [%0], [%1], 16;"
                 :: "r"(smem), "l"(g));
}
__device__ __forceinline__ uint32_t smaddr(const void* p) {
    return (uint32_t)__cvta_generic_to_shared(p);
}

// ---------------- weight pre-pack (tiled transpose + fp16) ------------------
__global__ void transpose_h_kernel(const float* __restrict__ src,
                                   __half* __restrict__ dst,
                                   int K, int M) {
    __shared__ float t[32][33];
    int l  = blockIdx.z;
    int kb = blockIdx.x * 32, mb = blockIdx.y * 32;
    int x = threadIdx.x, y = threadIdx.y;
    const float* s = src + (size_t)l * K * M;
    __half* d = dst + (size_t)l * M * K;
#pragma unroll
    for (int i = 0; i < 32; i += 8)
        t[y + i][x] = s[(size_t)(kb + y + i) * M + mb + x];
    __syncthreads();
#pragma unroll
    for (int i = 0; i < 32; i += 8)
        d[(size_t)(mb + y + i) * K + kb + x] = __float2half_rn(t[x][y + i]);
}

__global__ void pack_qkv_h_kernel(const float* __restrict__ W,
                                  __half* __restrict__ dst, int qkv) {
    __shared__ float t[32][33];
    int z = blockIdx.z;
    int l = z / H_, h = z - l * H_;
    int kb = blockIdx.x * 32, mb = blockIdx.y * 32;
    int x = threadIdx.x, y = threadIdx.y;
    const float* s = W + (size_t)(l * H_ + h) * D_ * HS_;
    __half* d = dst + ((size_t)l * (3*D_) + qkv * D_ + h * HS_) * D_;
#pragma unroll
    for (int i = 0; i < 32; i += 8)
        t[y + i][x] = s[(size_t)(kb + y + i) * HS_ + mb + x];
    __syncthreads();
#pragma unroll
    for (int i = 0; i < 32; i += 8)
        d[(size_t)(mb + y + i) * D_ + kb + x] = __float2half_rn(t[x][y + i]);
}

// ---------------- embedding ------------------------------------------------
__global__ void embed_kernel(const int* __restrict__ idx,
                             const float* __restrict__ tok,
                             const float* __restrict__ pos,
                             float* __restrict__ x) {
    int i = blockIdx.x * 256 + threadIdx.x;
    int n = i / (D_/4);
    int dq = i % (D_/4);
    int t = n & (T_-1);
    int id = idx[n];
    float4 a = ((const float4*)tok)[id * (D_/4) + dq];
    float4 p = ((const float4*)pos)[t  * (D_/4) + dq];
    float4 r;
    r.x = a.x + p.x; r.y = a.y + p.y; r.z = a.z + p.z; r.w = a.w + p.w;
    ((float4*)x)[i] = r;
}

// ---------------- layernorm (warp per row, fp16 output) ---------------------
__global__ void ln_kernel(const float* __restrict__ x,
                          const float* __restrict__ g,
                          const float* __restrict__ b,
                          __half* __restrict__ out) {
    int row  = blockIdx.x * 8 + (threadIdx.x >> 5);
    int lane = threadIdx.x & 31;
    const float* xr = x + (size_t)row * D_;
    float vals[12];
    float s = 0.f, s2 = 0.f;
#pragma unroll
    for (int i = 0; i < 12; i++) {
        float t = xr[lane + 32*i];
        vals[i] = t; s += t; s2 += t*t;
    }
#pragma unroll
    for (int off = 16; off; off >>= 1) {
        s  += __shfl_xor_sync(0xffffffffu, s,  off);
        s2 += __shfl_xor_sync(0xffffffffu, s2, off);
    }
    float mean = s * (1.f/D_);
    float var  = s2 * (1.f/D_) - mean*mean;
    float rstd = rsqrtf(var + 1e-5f);
    __half* orow = out + (size_t)row * D_;
#pragma unroll
    for (int i = 0; i < 12; i++) {
        int d = lane + 32*i;
        orow[d] = __float2half_rn((vals[i] - mean) * rstd * g[d] + b[d]);
    }
}

// ---------------- fp16 tensor-core GEMM, CTA 128x128, ldmatrix --------------
// C[N x M] = A[N x K] @ Bt[M x K]^T, fp16 in, fp32 accumulate.
// 8 warps, warp tile 64x32. BK=32 halves, 2-stage cp.async.
// Smem half[128][40] per tile: 80B stride -> ldmatrix conflict-free.
// MODE: 0 QKV scatter (fp16 out), 1 +bias(fp32), 2 relu+bias(fp16 out),
//       3 +bias+residual(fp32)
#define TILE_H (128*40)
#define GEMM_SMEM (4*TILE_H*2)

__device__ __forceinline__ void fill_h(__half* As, __half* Bs,
        const __half* A, const __half* Bt, int r0, int n0, int K,
        int k0, int tid) {
#pragma unroll
    for (int i = 0; i < 2; i++) {
        int f = i*256 + tid;
        int m = f >> 2, c8 = f & 3;
        cpasync16(smaddr(As + m*40 + c8*8),
                  A + (size_t)(r0+m)*K + k0 + c8*8);
    }
#pragma unroll
    for (int i = 0; i < 2; i++) {
        int f = i*256 + tid;
        int m = f >> 2, c8 = f & 3;
        cpasync16(smaddr(Bs + m*40 + c8*8),
                  Bt + (size_t)(n0+m)*K + k0 + c8*8);
    }
}

template<int MODE, bool QKV>
__global__ __launch_bounds__(256)
void gemm7(const __half* __restrict__ A, const __half* __restrict__ Bt,
           const float* __restrict__ bias, const float* __restrict__ res,
           void* __restrict__ C0v, __half* __restrict__ C1,
           __half* __restrict__ C2, int K, int M) {
    extern __shared__ __half smh[];
    __half* As = smh;
    __half* Bs = smh + 2*TILE_H;

    const int tid  = threadIdx.x;
    const int lane = tid & 31, warp = tid >> 5;
    const int gid  = lane >> 2, tig = lane & 3;
    const int wm   = warp >> 2, wn = warp & 3;
    const int m0   = wm * 64,   n0w = wn * 32;
    const int r0   = blockIdx.y * 128;
    const int n0   = blockIdx.x * 128;

    float acc[4][4][4];
#pragma unroll
    for (int i = 0; i < 4; i++)
#pragma unroll
        for (int j = 0; j < 4; j++)
#pragma unroll
            for (int c = 0; c < 4; c++) acc[i][j][c] = 0.f;

    fill_h(As, Bs, A, Bt, r0, n0, K, 0, tid);
    asm volatile("cp.async.commit_group;");

    int s = 0;
    for (int k0 = 0; k0 < K; k0 += 32) {
        if (k0 + 32 < K) {
            fill_h(As + (1-s)*TILE_H, Bs + (1-s)*TILE_H,
                   A, Bt, r0, n0, K, k0 + 32, tid);
            asm volatile("cp.async.commit_group;");
            asm volatile("cp.async.wait_group 1;");
        } else {
            asm volatile("cp.async.wait_group 0;");
        }
        __syncthreads();

        const uint32_t abase = smaddr(As + s*TILE_H);
        const uint32_t bbase = smaddr(Bs + s*TILE_H);
#pragma unroll
        for (int ks = 0; ks < 2; ks++) {
            const int kh = ks * 16;                 // half offset
            uint32_t af[4][4], bf[4][2];
            const int ar = (lane & 15);
            const int ak = kh + ((lane >> 4) << 3);
#pragma unroll
            for (int mi = 0; mi < 4; mi++)
                ldsm_x4(af[mi][0], af[mi][1], af[mi][2], af[mi][3],
                        abase + ((m0 + mi*16 + ar)*40 + ak)*2);
            const int j  = lane >> 3;
            const int bk = kh + ((j & 1) << 3);
#pragma unroll
            for (int np = 0; np < 2; np++) {
                int nb = n0w + ((np*2) + (j >> 1))*8 + (lane & 7);
                ldsm_x4(bf[np*2][0], bf[np*2][1], bf[np*2+1][0], bf[np*2+1][1],
                        bbase + (nb*40 + bk)*2);
            }
#pragma unroll
            for (int mi = 0; mi < 4; mi++)
#pragma unroll
                for (int ni = 0; ni < 4; ni++)
                    mma_f16(acc[mi][ni], af[mi], bf[ni]);
        }
        __syncthreads();
        s ^= 1;
    }

    // ---- epilogue ----
    if (QKV) {
        __half* C0 = (__half*)C0v;
        int qkv = blockIdx.x / 3;
        int cbase = blockIdx.x * 128 - qkv * 384;
        __half* Cd = (qkv == 0) ? C0 : (qkv == 1 ? C1 : C2);
#pragma unroll
        for (int mi = 0; mi < 4; mi++) {
#pragma unroll
            for (int ni = 0; ni < 4; ni++) {
                int c = cbase + n0w + ni*8 + tig*2;
                int h = c >> 6, hs = c & 63;
#pragma unroll
                for (int rh = 0; rh < 2; rh++) {
                    int rr = r0 + m0 + mi*16 + gid + rh*8;
                    int bb = rr >> 8, t = rr & 255;
                    size_t oi = (((size_t)bb*H_ + h)*T_ + t)*64 + hs;
                    *(__half2*)(Cd + oi) =
                        __floats2half2_rn(acc[mi][ni][rh*2+0],
                                          acc[mi][ni][rh*2+1]);
                }
            }
        }
    } else {
#pragma unroll
        for (int mi = 0; mi < 4; mi++) {
#pragma unroll
            for (int ni = 0; ni < 4; ni++) {
                int col = n0 + n0w + ni*8 + tig*2;
                float2 bv = make_float2(0.f, 0.f);
                if (MODE >= 1) {
                    bv.x = bias[col];
                    bv.y = bias[col + 1];
                }
#pragma unroll
                for (int rh = 0; rh < 2; rh++) {
                    int rr = r0 + m0 + mi*16 + gid + rh*8;
                    float2 o;
                    o.x = acc[mi][ni][rh*2+0] + bv.x;
                    o.y = acc[mi][ni][rh*2+1] + bv.y;
                    size_t ci = (size_t)rr*M + col;
                    if (MODE == 2) {
                        o.x = fmaxf(o.x, 0.f); o.y = fmaxf(o.y, 0.f);
                        *(__half2*)((__half*)C0v + ci) =
                            __floats2half2_rn(o.x, o.y);
                    } else {
                        if (MODE == 3) {
                            float2 rv = *(const float2*)(res + ci);
                            o.x += rv.x; o.y += rv.y;
                        }
                        *(float2*)((float*)C0v + ci) = o;
                    }
                }
            }
        }
    }
}

// ---------------- fp16 MMA flash attention ----------------------------------
// 128 threads, 4 warps; Bq=Bkv=64; warp tile 16 rows x 64 cols.
// q,k,v fp16 [B,H,T,64]; o fp16 [B,T,D] concat. fp32 softmax/accum.
// Smem (halves, stride 72): Qs[m][d], Ks[s][d] (B operand direct),
//   Vt[d][s] (transposed at load), Ps[m][s] fp16.
#define ASTR 72
#define ATILE (64*ASTR)          // halves
#define ATT_SMEM (4*ATILE*2)

__global__ __launch_bounds__(128)
void attn_h(const __half* __restrict__ q, const __half* __restrict__ k,
            const __half* __restrict__ v, __half* __restrict__ o) {
    extern __shared__ __half smh[];
    __half* Qs = smh;
    __half* Ks = smh + ATILE;
    __half* Vt = smh + 2*ATILE;
    __half* Ps = smh + 3*ATILE;

    const int tid  = threadIdx.x;
    const int lane = tid & 31, warp = tid >> 5;
    const int gid  = lane >> 2, tig = lane & 3;
    const int m0w  = warp * 16;
    const int bh   = blockIdx.y;
    const int q0   = blockIdx.x * 64;
    const __half* qb = q + (size_t)bh*T_*64;
    const __half* kb = k + (size_t)bh*T_*64;
    const __half* vb = v + (size_t)bh*T_*64;

    // Q tile copy: 64x64 halves = 512 16B chunks
#pragma unroll
    for (int i = 0; i < 4; i++) {
        int f = i*128 + tid;
        int r = f >> 3, c8 = f & 7;
        *(uint4*)&Qs[r*ASTR + c8*8] =
            *(const uint4*)(qb + (q0+r)*64 + c8*8);
    }

    float mrow[2], lse[2];
    float oac[8][4];
    mrow[0] = mrow[1] = -1e30f;
    lse[0] = lse[1] = 0.f;
#pragma unroll
    for (int i = 0; i < 8; i++)
#pragma unroll
        for (int c = 0; c < 4; c++) oac[i][c] = 0.f;

    const uint32_t qsb = smaddr(Qs), ksb = smaddr(Ks);
    const uint32_t vtb = smaddr(Vt), psb = smaddr(Ps);
    (void)qsb; (void)ksb; (void)vtb; (void)psb;
    const uint32_t* Qw = (const uint32_t*)Qs;
    const uint32_t* Kw = (const uint32_t*)Ks;
    const uint32_t* Vw = (const uint32_t*)Vt;
    const uint32_t* Pw = (const uint32_t*)Ps;

    for (int s0 = 0; s0 <= q0; s0 += 64) {
        __syncthreads();
        // K tile: [s][d] direct; V tile: transpose to [d][s]
#pragma unroll
        for (int i = 0; i < 4; i++) {
            int f = i*128 + tid;
            int r = f >> 3, c8 = f & 7;
            *(uint4*)&Ks[r*ASTR + c8*8] =
                *(const uint4*)(kb + (s0+r)*64 + c8*8);
            uint4 vv = *(const uint4*)(vb + (s0+r)*64 + c8*8);
            const __half* vh = (const __half*)&vv;
#pragma unroll
            for (int jj = 0; jj < 8; jj++)
                Vt[(c8*8 + jj)*ASTR + r] = vh[jj];
        }
        __syncthreads();

        // ---- S = Q K^T ----
        float sac[8][4];
#pragma unroll
        for (int i = 0; i < 8; i++)
#pragma unroll
            for (int c = 0; c < 4; c++) sac[i][c] = 0.f;

#pragma unroll
        for (int ks = 0; ks < 4; ks++) {
            const int kw = ks * 8;          // word offset (36 words/row)
            uint32_t af[4], bf[8][2];
            af[0] = Qw[(m0w+gid  )*36 + kw + tig    ];
            af[1] = Qw[(m0w+gid+8)*36 + kw + tig    ];
            af[2] = Qw[(m0w+gid  )*36 + kw + tig + 4];
            af[3] = Qw[(m0w+gid+8)*36 + kw + tig + 4];
#pragma unroll
            for (int nb = 0; nb < 8; nb++) {
                int cr = nb*8 + gid;
                bf[nb][0] = Kw[cr*36 + kw + tig    ];
                bf[nb][1] = Kw[cr*36 + kw + tig + 4];
            }
#pragma unroll
            for (int nb = 0; nb < 8; nb++)
                mma_f16(sac[nb], af, bf[nb]);
        }

        // ---- online softmax (fp32) ----
        const bool diag = (s0 == q0);
        float tm0 = -1e30f, tm1 = -1e30f;
#pragma unroll
        for (int nb = 0; nb < 8; nb++) {
#pragma unroll
            for (int c = 0; c < 4; c++) {
                float val = sac[nb][c] * 0.125f;
                if (diag) {
                    int col = nb*8 + tig*2 + (c & 1);
                    int row = m0w + gid + ((c >> 1) ? 8 : 0);
                    if (col > row) val = -1e30f;
                }
                sac[nb][c] = val;
                if (c < 2) tm0 = fmaxf(tm0, val);
                else       tm1 = fmaxf(tm1, val);
            }
        }
        tm0 = fmaxf(tm0, __shfl_xor_sync(0xffffffffu, tm0, 1));
        tm0 = fmaxf(tm0, __shfl_xor_sync(0xffffffffu, tm0, 2));
        tm1 = fmaxf(tm1, __shfl_xor_sync(0xffffffffu, tm1, 1));
        tm1 = fmaxf(tm1, __shfl_xor_sync(0xffffffffu, tm1, 2));
        float nm0 = fmaxf(mrow[0], tm0), nm1 = fmaxf(mrow[1], tm1);
        float cr0 = __expf(mrow[0] - nm0), cr1 = __expf(mrow[1] - nm1);
        mrow[0] = nm0; mrow[1] = nm1;

        float rs0 = 0.f, rs1 = 0.f;
#pragma unroll
        for (int nb = 0; nb < 8; nb++) {
            float p0 = __expf(sac[nb][0] - nm0);
            float p1 = __expf(sac[nb][1] - nm0);
            float p2 = __expf(sac[nb][2] - nm1);
            float p3 = __expf(sac[nb][3] - nm1);
            rs0 += p0 + p1; rs1 += p2 + p3;
            *(__half2*)&Ps[(m0w+gid  )*ASTR + nb*8 + tig*2] =
                __floats2half2_rn(p0, p1);
            *(__half2*)&Ps[(m0w+gid+8)*ASTR + nb*8 + tig*2] =
                __floats2half2_rn(p2, p3);
        }
        rs0 += __shfl_xor_sync(0xffffffffu, rs0, 1);
        rs0 += __shfl_xor_sync(0xffffffffu, rs0, 2);
        rs1 += __shfl_xor_sync(0xffffffffu, rs1, 1);
        rs1 += __shfl_xor_sync(0xffffffffu, rs1, 2);
        lse[0] = lse[0]*cr0 + rs0;
        lse[1] = lse[1]*cr1 + rs1;
#pragma unroll
        for (int i = 0; i < 8; i++) {
            oac[i][0] *= cr0; oac[i][1] *= cr0;
            oac[i][2] *= cr1; oac[i][3] *= cr1;
        }
        __syncwarp();

        // ---- O += P V ----
#pragma unroll
        for (int ks = 0; ks < 4; ks++) {
            const int kw = ks * 8;
            uint32_t af[4], bf[8][2];
            af[0] = Pw[(m0w+gid  )*36 + kw + tig    ];
            af[1] = Pw[(m0w+gid+8)*36 + kw + tig    ];
            af[2] = Pw[(m0w+gid  )*36 + kw + tig + 4];
            af[3] = Pw[(m0w+gid+8)*36 + kw + tig + 4];
#pragma unroll
            for (int nb = 0; nb < 8; nb++) {
                int cr = nb*8 + gid;
                bf[nb][0] = Vw[cr*36 + kw + tig    ];
                bf[nb][1] = Vw[cr*36 + kw + tig + 4];
            }
#pragma unroll
            for (int nb = 0; nb < 8; nb++)
                mma_f16(oac[nb], af, bf[nb]);
        }
        __syncwarp();
    }

    const int bb = bh / H_, hh = bh % H_;
    const float inv0 = 1.f / lse[0], inv1 = 1.f / lse[1];
    const int t0 = q0 + m0w + gid;
#pragma unroll
    for (int nb = 0; nb < 8; nb++) {
        int col = hh*64 + nb*8 + tig*2;
        size_t oi0 = ((size_t)bb*T_ + t0    )*D_ + col;
        size_t oi1 = ((size_t)bb*T_ + t0 + 8)*D_ + col;
        *(__half2*)(o + oi0) = __floats2half2_rn(oac[nb][0]*inv0,
                                                 oac[nb][1]*inv0);
        *(__half2*)(o + oi1) = __floats2half2_rn(oac[nb][2]*inv1,
                                                 oac[nb][3]*inv1);
    }
}

// ---------------- launch ----------------------------------------------------
extern "C" void kernel_launch(void* const* d_in, const int* in_sizes, int n_in,
                              void* d_out, int out_size) {
    const int*   idx   = (const int*)  d_in[0];
    const float* tok   = (const float*)d_in[1];
    const float* pos   = (const float*)d_in[2];
    const float* Wq    = (const float*)d_in[3];
    const float* Wk    = (const float*)d_in[4];
    const float* Wv    = (const float*)d_in[5];
    const float* Wproj = (const float*)d_in[6];
    const float* bproj = (const float*)d_in[7];
    const float* ln1g  = (const float*)d_in[8];
    const float* ln1b  = (const float*)d_in[9];
    const float* ln2g  = (const float*)d_in[10];
    const float* ln2b  = (const float*)d_in[11];
    const float* W1    = (const float*)d_in[12];
    const float* b1    = (const float*)d_in[13];
    const float* W2    = (const float*)d_in[14];
    const float* b2    = (const float*)d_in[15];
    const float* lnfg  = (const float*)d_in[16];
    const float* lnfb  = (const float*)d_in[17];
    const float* Wlm   = (const float*)d_in[18];
    const float* blm   = (const float*)d_in[19];
    float* out = (float*)d_out;

    float *x;
    __half *xn, *q, *k, *v, *o, *h, *w;
    cudaGetSymbolAddress((void**)&x,  g_x);
    cudaGetSymbolAddress((void**)&xn, g_xn);
    cudaGetSymbolAddress((void**)&q,  g_q);
    cudaGetSymbolAddress((void**)&k,  g_k);
    cudaGetSymbolAddress((void**)&v,  g_v);
    cudaGetSymbolAddress((void**)&o,  g_o);
    cudaGetSymbolAddress((void**)&h,  g_h);
    cudaGetSymbolAddress((void**)&w,  g_w);

    cudaFuncSetAttribute(attn_h,
        cudaFuncAttributeMaxDynamicSharedMemorySize, ATT_SMEM);
    cudaFuncSetAttribute(gemm7<0,true>,
        cudaFuncAttributeMaxDynamicSharedMemorySize, GEMM_SMEM);
    cudaFuncSetAttribute(gemm7<1,false>,
        cudaFuncAttributeMaxDynamicSharedMemorySize, GEMM_SMEM);
    cudaFuncSetAttribute(gemm7<2,false>,
        cudaFuncAttributeMaxDynamicSharedMemorySize, GEMM_SMEM);
    cudaFuncSetAttribute(gemm7<3,false>,
        cudaFuncAttributeMaxDynamicSharedMemorySize, GEMM_SMEM);

    // weight pre-pack (transposed, fp16)
    {
        dim3 blk(32, 8);
        pack_qkv_h_kernel<<<dim3(D_/32, HS_/32, L_*H_), blk>>>(Wq, w+WQKV_OFF, 0);
        pack_qkv_h_kernel<<<dim3(D_/32, HS_/32, L_*H_), blk>>>(Wk, w+WQKV_OFF, 1);
        pack_qkv_h_kernel<<<dim3(D_/32, HS_/32, L_*H_), blk>>>(Wv, w+WQKV_OFF, 2);
        transpose_h_kernel<<<dim3(D_/32,  D_/32,  L_), blk>>>(Wproj, w+WPROJ_OFF, D_,  D_);
        transpose_h_kernel<<<dim3(D_/32,  FF_/32, L_), blk>>>(W1,    w+W1_OFF,    D_,  FF_);
        transpose_h_kernel<<<dim3(FF_/32, D_/32,  L_), blk>>>(W2,    w+W2_OFF,    FF_, D_);
        transpose_h_kernel<<<dim3(D_/32,  V_/32,  1 ), blk>>>(Wlm,   w+WLM_OFF,   D_,  V_);
    }

    embed_kernel<<<(N_*D_/4)/256, 256>>>(idx, tok, pos, x);

    for (int l = 0; l < L_; l++) {
        ln_kernel<<<N_/8, 256>>>(x, ln1g + l*D_, ln1b + l*D_, xn);

        gemm7<0,true><<<dim3(9, N_/128), 256, GEMM_SMEM>>>(
            xn, w + WQKV_OFF + (size_t)l*D_*3*D_, nullptr, nullptr,
            q, k, v, D_, 3*D_);

        attn_h<<<dim3(T_/64, B_*H_), 128, ATT_SMEM>>>(q, k, v, o);

        gemm7<3,false><<<dim3(3, N_/128), 256, GEMM_SMEM>>>(
            o, w + WPROJ_OFF + (size_t)l*D_*D_, bproj + l*D_, x,
            x, nullptr, nullptr, D_, D_);

        ln_kernel<<<N_/8, 256>>>(x, ln2g + l*D_, ln2b + l*D_, xn);

        gemm7<2,false><<<dim3(12, N_/128), 256, GEMM_SMEM>>>(
            xn, w + W1_OFF + (size_t)l*D_*FF_, b1 + l*FF_, nullptr,
            h, nullptr, nullptr, D_, FF_);

        gemm7<3,false><<<dim3(3, N_/128), 256, GEMM_SMEM>>>(
            h, w + W2_OFF + (size_t)l*FF_*D_, b2 + l*D_, x,
            x, nullptr, nullptr, FF_, D_);
    }

    ln_kernel<<<N_/8, 256>>>(x, lnfg, lnfb, xn);
    gemm7<1,false><<<dim3(1, N_/128), 256, GEMM_SMEM>>>(
        xn, w + WLM_OFF, blm, nullptr, out, nullptr, nullptr, D_, V_);
}

// round 14
// speedup vs baseline: 2.0561x; 1.0974x over previous
#include <cuda_runtime.h>
#include <cuda_fp16.h>
#include <cstdint>
#include <math.h>

#define B_ 256
#define T_ 256
#define V_ 128
#define D_ 384
#define H_ 6
#define HS_ 64
#define L_ 6
#define FF_ 1536
#define N_ (B_*T_)   // 65536 tokens

// ---------------- scratch ---------------------------------------------------
__device__ float  g_x [N_*D_];
__device__ __half g_xn[N_*D_];
__device__ __half g_q [N_*D_];
__device__ __half g_k [N_*D_];
__device__ __half g_v [N_*D_];
__device__ __half g_o [N_*D_];
__device__ __half g_h [N_*FF_];

// packed fp16, TRANSPOSED weights (Bt[n][k], K contiguous)
#define WQKV_OFF  0
#define WQKV_SZ   (L_*D_*3*D_)
#define WPROJ_OFF (WQKV_OFF + WQKV_SZ)
#define WPROJ_SZ  (L_*D_*D_)
#define W1_OFF    (WPROJ_OFF + WPROJ_SZ)
#define W1_SZ     (L_*D_*FF_)
#define W2_OFF    (W1_OFF + W1_SZ)
#define W2_SZ     (L_*FF_*D_)
#define WLM_OFF   (W2_OFF + W2_SZ)
#define WLM_SZ    (D_*V_)
#define WTOT      (WLM_OFF + WLM_SZ)
__device__ __half g_w[WTOT];

// ---------------- helpers ---------------------------------------------------
__device__ __forceinline__ void mma_f16(float c[4], const uint32_t a[4],
                                        const uint32_t b[2]) {
    asm volatile(
        "mma.sync.aligned.m16n8k16.row.col.f32.f16.f16.f32 "
        "{%0,%1,%2,%3}, {%4,%5,%6,%7}, {%8,%9}, {%0,%1,%2,%3};"
        : "+f"(c[0]), "+f"(c[1]), "+f"(c[2]), "+f"(c[3])
        : "r"(a[0]), "r"(a[1]), "r"(a[2]), "r"(a[3]),
          "r"(b[0]), "r"(b[1]));
}
__device__ __forceinline__ void ldsm_x4(uint32_t& r0, uint32_t& r1,
                                        uint32_t& r2, uint32_t& r3,
                                        uint32_t addr) {
    asm volatile(
        "ldmatrix.sync.aligned.m8n8.x4.shared.b16 {%0,%1,%2,%3}, [%4];"
        : "=r"(r0), "=r"(r1), "=r"(r2), "=r"(r3) : "r"(addr));
}
__device__ __forceinline__ void cpasync16(uint32_t smem, const void* g) {
    asm volatile("cp.async.cg.shared.global [%0], [%1], 16;"
                 :: "r"(smem), "l"(g));
}
__device__ __forceinline__ uint32_t smaddr(const void* p) {
    return (uint32_t)__cvta_generic_to_shared(p);
}

// ---------------- weight pre-pack (tiled transpose + fp16) ------------------
__global__ void transpose_h_kernel(const float* __restrict__ src,
                                   __half* __restrict__ dst,
                                   int K, int M) {
    __shared__ float t[32][33];
    int l  = blockIdx.z;
    int kb = blockIdx.x * 32, mb = blockIdx.y * 32;
    int x = threadIdx.x, y = threadIdx.y;
    const float* s = src + (size_t)l * K * M;
    __half* d = dst + (size_t)l * M * K;
#pragma unroll
    for (int i = 0; i < 32; i += 8)
        t[y + i][x] = s[(size_t)(kb + y + i) * M + mb + x];
    __syncthreads();
#pragma unroll
    for (int i = 0; i < 32; i += 8)
        d[(size_t)(mb + y + i) * K + kb + x] = __float2half_rn(t[x][y + i]);
}

__global__ void pack_qkv_h_kernel(const float* __restrict__ W,
                                  __half* __restrict__ dst, int qkv) {
    __shared__ float t[32][33];
    int z = blockIdx.z;
    int l = z / H_, h = z - l * H_;
    int kb = blockIdx.x * 32, mb = blockIdx.y * 32;
    int x = threadIdx.x, y = threadIdx.y;
    const float* s = W + (size_t)(l * H_ + h) * D_ * HS_;
    __half* d = dst + ((size_t)l * (3*D_) + qkv * D_ + h * HS_) * D_;
#pragma unroll
    for (int i = 0; i < 32; i += 8)
        t[y + i][x] = s[(size_t)(kb + y + i) * HS_ + mb + x];
    __syncthreads();
#pragma unroll
    for (int i = 0; i < 32; i += 8)
        d[(size_t)(mb + y + i) * D_ + kb + x] = __float2half_rn(t[x][y + i]);
}

// ---------------- embedding ------------------------------------------------
__global__ void embed_kernel(const int* __restrict__ idx,
                             const float* __restrict__ tok,
                             const float* __restrict__ pos,
                             float* __restrict__ x) {
    int i = blockIdx.x * 256 + threadIdx.x;
    int n = i / (D_/4);
    int dq = i % (D_/4);
    int t = n & (T_-1);
    int id = idx[n];
    float4 a = ((const float4*)tok)[id * (D_/4) + dq];
    float4 p = ((const float4*)pos)[t  * (D_/4) + dq];
    float4 r;
    r.x = a.x + p.x; r.y = a.y + p.y; r.z = a.z + p.z; r.w = a.w + p.w;
    ((float4*)x)[i] = r;
}

// ---------------- layernorm (warp per row, fp16 output) ---------------------
__global__ void ln_kernel(const float* __restrict__ x,
                          const float* __restrict__ g,
                          const float* __restrict__ b,
                          __half* __restrict__ out) {
    int row  = blockIdx.x * 8 + (threadIdx.x >> 5);
    int lane = threadIdx.x & 31;
    const float* xr = x + (size_t)row * D_;
    float vals[12];
    float s = 0.f, s2 = 0.f;
#pragma unroll
    for (int i = 0; i < 12; i++) {
        float t = xr[lane + 32*i];
        vals[i] = t; s += t; s2 += t*t;
    }
#pragma unroll
    for (int off = 16; off; off >>= 1) {
        s  += __shfl_xor_sync(0xffffffffu, s,  off);
        s2 += __shfl_xor_sync(0xffffffffu, s2, off);
    }
    float mean = s * (1.f/D_);
    float var  = s2 * (1.f/D_) - mean*mean;
    float rstd = rsqrtf(var + 1e-5f);
    __half* orow = out + (size_t)row * D_;
#pragma unroll
    for (int i = 0; i < 12; i++) {
        int d = lane + 32*i;
        orow[d] = __float2half_rn((vals[i] - mean) * rstd * g[d] + b[d]);
    }
}

// ---------------- fp16 tensor-core GEMM, CTA 128x128, 3-stage ---------------
// C[N x M] = A[N x K] @ Bt[M x K]^T, fp16 in, fp32 accumulate.
// 8 warps, warp tile 64x32. BK=32 halves, 3-stage cp.async, 1 sync/iter.
// Smem half[128][40] per tile: 80B stride -> ldmatrix conflict-free.
// MODE: 0 QKV scatter (fp16 out), 1 +bias(fp32), 2 relu+bias(fp16 out),
//       3 +bias+residual(fp32)
#define TILE_H (128*40)
#define GEMM_SMEM (6*TILE_H*2)     // 3 stages x (A,B)

__device__ __forceinline__ void fill_h(__half* As, __half* Bs,
        const __half* A, const __half* Bt, int r0, int n0, int K,
        int k0, int tid) {
#pragma unroll
    for (int i = 0; i < 2; i++) {
        int f = i*256 + tid;
        int m = f >> 2, c8 = f & 3;
        cpasync16(smaddr(As + m*40 + c8*8),
                  A + (size_t)(r0+m)*K + k0 + c8*8);
    }
#pragma unroll
    for (int i = 0; i < 2; i++) {
        int f = i*256 + tid;
        int m = f >> 2, c8 = f & 3;
        cpasync16(smaddr(Bs + m*40 + c8*8),
                  Bt + (size_t)(n0+m)*K + k0 + c8*8);
    }
}

template<int MODE, bool QKV>
__global__ __launch_bounds__(256, 2)
void gemm8(const __half* __restrict__ A, const __half* __restrict__ Bt,
           const float* __restrict__ bias, const float* __restrict__ res,
           void* __restrict__ C0v, __half* __restrict__ C1,
           __half* __restrict__ C2, int K, int M) {
    extern __shared__ __half smh[];
    __half* As = smh;                 // 3 stages
    __half* Bs = smh + 3*TILE_H;

    const int tid  = threadIdx.x;
    const int lane = tid & 31, warp = tid >> 5;
    const int gid  = lane >> 2, tig = lane & 3;
    const int wm   = warp >> 2, wn = warp & 3;
    const int m0   = wm * 64,   n0w = wn * 32;
    const int r0   = blockIdx.y * 128;
    const int n0   = blockIdx.x * 128;
    const int nch  = K >> 5;

    float acc[4][4][4];
#pragma unroll
    for (int i = 0; i < 4; i++)
#pragma unroll
        for (int j = 0; j < 4; j++)
#pragma unroll
            for (int c = 0; c < 4; c++) acc[i][j][c] = 0.f;

    fill_h(As, Bs, A, Bt, r0, n0, K, 0, tid);
    asm volatile("cp.async.commit_group;");
    fill_h(As + TILE_H, Bs + TILE_H, A, Bt, r0, n0, K, 32, tid);
    asm volatile("cp.async.commit_group;");

    for (int c = 0; c < nch; c++) {
        if (c < nch - 1) asm volatile("cp.async.wait_group 1;");
        else             asm volatile("cp.async.wait_group 0;");
        __syncthreads();

        const int nf = c + 2;
        if (nf < nch) {
            const int st = nf - (nf/3)*3;
            fill_h(As + st*TILE_H, Bs + st*TILE_H,
                   A, Bt, r0, n0, K, nf*32, tid);
            asm volatile("cp.async.commit_group;");
        }

        const int sc = c - (c/3)*3;
        const uint32_t abase = smaddr(As + sc*TILE_H);
        const uint32_t bbase = smaddr(Bs + sc*TILE_H);
#pragma unroll
        for (int ks = 0; ks < 2; ks++) {
            const int kh = ks * 16;
            uint32_t af[4][4], bf[4][2];
            const int ar = (lane & 15);
            const int ak = kh + ((lane >> 4) << 3);
#pragma unroll
            for (int mi = 0; mi < 4; mi++)
                ldsm_x4(af[mi][0], af[mi][1], af[mi][2], af[mi][3],
                        abase + ((m0 + mi*16 + ar)*40 + ak)*2);
            const int j  = lane >> 3;
            const int bk = kh + ((j & 1) << 3);
#pragma unroll
            for (int np = 0; np < 2; np++) {
                int nb = n0w + ((np*2) + (j >> 1))*8 + (lane & 7);
                ldsm_x4(bf[np*2][0], bf[np*2][1], bf[np*2+1][0], bf[np*2+1][1],
                        bbase + (nb*40 + bk)*2);
            }
#pragma unroll
            for (int mi = 0; mi < 4; mi++)
#pragma unroll
                for (int ni = 0; ni < 4; ni++)
                    mma_f16(acc[mi][ni], af[mi], bf[ni]);
        }
    }

    // ---- epilogue ----
    if (QKV) {
        __half* C0 = (__half*)C0v;
        int qkv = blockIdx.x / 3;
        int cbase = blockIdx.x * 128 - qkv * 384;
        __half* Cd = (qkv == 0) ? C0 : (qkv == 1 ? C1 : C2);
#pragma unroll
        for (int mi = 0; mi < 4; mi++) {
#pragma unroll
            for (int ni = 0; ni < 4; ni++) {
                int c = cbase + n0w + ni*8 + tig*2;
                int h = c >> 6, hs = c & 63;
#pragma unroll
                for (int rh = 0; rh < 2; rh++) {
                    int rr = r0 + m0 + mi*16 + gid + rh*8;
                    int bb = rr >> 8, t = rr & 255;
                    size_t oi = (((size_t)bb*H_ + h)*T_ + t)*64 + hs;
                    *(__half2*)(Cd + oi) =
                        __floats2half2_rn(acc[mi][ni][rh*2+0],
                                          acc[mi][ni][rh*2+1]);
                }
            }
        }
    } else {
#pragma unroll
        for (int mi = 0; mi < 4; mi++) {
#pragma unroll
            for (int ni = 0; ni < 4; ni++) {
                int col = n0 + n0w + ni*8 + tig*2;
                float2 bv = make_float2(0.f, 0.f);
                if (MODE >= 1) {
                    bv.x = bias[col];
                    bv.y = bias[col + 1];
                }
#pragma unroll
                for (int rh = 0; rh < 2; rh++) {
                    int rr = r0 + m0 + mi*16 + gid + rh*8;
                    float2 o;
                    o.x = acc[mi][ni][rh*2+0] + bv.x;
                    o.y = acc[mi][ni][rh*2+1] + bv.y;
                    size_t ci = (size_t)rr*M + col;
                    if (MODE == 2) {
                        o.x = fmaxf(o.x, 0.f); o.y = fmaxf(o.y, 0.f);
                        *(__half2*)((__half*)C0v + ci) =
                            __floats2half2_rn(o.x, o.y);
                    } else {
                        if (MODE == 3) {
                            float2 rv = *(const float2*)(res + ci);
                            o.x += rv.x; o.y += rv.y;
                        }
                        *(float2*)((float*)C0v + ci) = o;
                    }
                }
            }
        }
    }
}

// ---------------- fp16 MMA flash attention ----------------------------------
#define ASTR 72
#define ATILE (64*ASTR)
#define ATT_SMEM (4*ATILE*2)

__global__ __launch_bounds__(128)
void attn_h(const __half* __restrict__ q, const __half* __restrict__ k,
            const __half* __restrict__ v, __half* __restrict__ o) {
    extern __shared__ __half smh[];
    __half* Qs = smh;
    __half* Ks = smh + ATILE;
    __half* Vt = smh + 2*ATILE;
    __half* Ps = smh + 3*ATILE;

    const int tid  = threadIdx.x;
    const int lane = tid & 31, warp = tid >> 5;
    const int gid  = lane >> 2, tig = lane & 3;
    const int m0w  = warp * 16;
    const int bh   = blockIdx.y;
    const int q0   = blockIdx.x * 64;
    const __half* qb = q + (size_t)bh*T_*64;
    const __half* kb = k + (size_t)bh*T_*64;
    const __half* vb = v + (size_t)bh*T_*64;

#pragma unroll
    for (int i = 0; i < 4; i++) {
        int f = i*128 + tid;
        int r = f >> 3, c8 = f & 7;
        *(uint4*)&Qs[r*ASTR + c8*8] =
            *(const uint4*)(qb + (q0+r)*64 + c8*8);
    }

    float mrow[2], lse[2];
    float oac[8][4];
    mrow[0] = mrow[1] = -1e30f;
    lse[0] = lse[1] = 0.f;
#pragma unroll
    for (int i = 0; i < 8; i++)
#pragma unroll
        for (int c = 0; c < 4; c++) oac[i][c] = 0.f;

    const uint32_t* Qw = (const uint32_t*)Qs;
    const uint32_t* Kw = (const uint32_t*)Ks;
    const uint32_t* Vw = (const uint32_t*)Vt;
    const uint32_t* Pw = (const uint32_t*)Ps;

    for (int s0 = 0; s0 <= q0; s0 += 64) {
        __syncthreads();
#pragma unroll
        for (int i = 0; i < 4; i++) {
            int f = i*128 + tid;
            int r = f >> 3, c8 = f & 7;
            *(uint4*)&Ks[r*ASTR + c8*8] =
                *(const uint4*)(kb + (s0+r)*64 + c8*8);
            uint4 vv = *(const uint4*)(vb + (s0+r)*64 + c8*8);
            const __half* vh = (const __half*)&vv;
#pragma unroll
            for (int jj = 0; jj < 8; jj++)
                Vt[(c8*8 + jj)*ASTR + r] = vh[jj];
        }
        __syncthreads();

        float sac[8][4];
#pragma unroll
        for (int i = 0; i < 8; i++)
#pragma unroll
            for (int c = 0; c < 4; c++) sac[i][c] = 0.f;

#pragma unroll
        for (int ks = 0; ks < 4; ks++) {
            const int kw = ks * 8;
            uint32_t af[4], bf[8][2];
            af[0] = Qw[(m0w+gid  )*36 + kw + tig    ];
            af[1] = Qw[(m0w+gid+8)*36 + kw + tig    ];
            af[2] = Qw[(m0w+gid  )*36 + kw + tig + 4];
            af[3] = Qw[(m0w+gid+8)*36 + kw + tig + 4];
#pragma unroll
            for (int nb = 0; nb < 8; nb++) {
                int cr = nb*8 + gid;
                bf[nb][0] = Kw[cr*36 + kw + tig    ];
                bf[nb][1] = Kw[cr*36 + kw + tig + 4];
            }
#pragma unroll
            for (int nb = 0; nb < 8; nb++)
                mma_f16(sac[nb], af, bf[nb]);
        }

        const bool diag = (s0 == q0);
        float tm0 = -1e30f, tm1 = -1e30f;
#pragma unroll
        for (int nb = 0; nb < 8; nb++) {
#pragma unroll
            for (int c = 0; c < 4; c++) {
                float val = sac[nb][c] * 0.125f;
                if (diag) {
                    int col = nb*8 + tig*2 + (c & 1);
                    int row = m0w + gid + ((c >> 1) ? 8 : 0);
                    if (col > row) val = -1e30f;
                }
                sac[nb][c] = val;
                if (c < 2) tm0 = fmaxf(tm0, val);
                else       tm1 = fmaxf(tm1, val);
            }
        }
        tm0 = fmaxf(tm0, __shfl_xor_sync(0xffffffffu, tm0, 1));
        tm0 = fmaxf(tm0, __shfl_xor_sync(0xffffffffu, tm0, 2));
        tm1 = fmaxf(tm1, __shfl_xor_sync(0xffffffffu, tm1, 1));
        tm1 = fmaxf(tm1, __shfl_xor_sync(0xffffffffu, tm1, 2));
        float nm0 = fmaxf(mrow[0], tm0), nm1 = fmaxf(mrow[1], tm1);
        float cr0 = __expf(mrow[0] - nm0), cr1 = __expf(mrow[1] - nm1);
        mrow[0] = nm0; mrow[1] = nm1;

        float rs0 = 0.f, rs1 = 0.f;
#pragma unroll
        for (int nb = 0; nb < 8; nb++) {
            float p0 = __expf(sac[nb][0] - nm0);
            float p1 = __expf(sac[nb][1] - nm0);
            float p2 = __expf(sac[nb][2] - nm1);
            float p3 = __expf(sac[nb][3] - nm1);
            rs0 += p0 + p1; rs1 += p2 + p3;
            *(__half2*)&Ps[(m0w+gid  )*ASTR + nb*8 + tig*2] =
                __floats2half2_rn(p0, p1);
            *(__half2*)&Ps[(m0w+gid+8)*ASTR + nb*8 + tig*2] =
                __floats2half2_rn(p2, p3);
        }
        rs0 += __shfl_xor_sync(0xffffffffu, rs0, 1);
        rs0 += __shfl_xor_sync(0xffffffffu, rs0, 2);
        rs1 += __shfl_xor_sync(0xffffffffu, rs1, 1);
        rs1 += __shfl_xor_sync(0xffffffffu, rs1, 2);
        lse[0] = lse[0]*cr0 + rs0;
        lse[1] = lse[1]*cr1 + rs1;
#pragma unroll
        for (int i = 0; i < 8; i++) {
            oac[i][0] *= cr0; oac[i][1] *= cr0;
            oac[i][2] *= cr1; oac[i][3] *= cr1;
        }
        __syncwarp();

#pragma unroll
        for (int ks = 0; ks < 4; ks++) {
            const int kw = ks * 8;
            uint32_t af[4], bf[8][2];
            af[0] = Pw[(m0w+gid  )*36 + kw + tig    ];
            af[1] = Pw[(m0w+gid+8)*36 + kw + tig    ];
            af[2] = Pw[(m0w+gid  )*36 + kw + tig + 4];
            af[3] = Pw[(m0w+gid+8)*36 + kw + tig + 4];
#pragma unroll
            for (int nb = 0; nb < 8; nb++) {
                int cr = nb*8 + gid;
                bf[nb][0] = Vw[cr*36 + kw + tig    ];
                bf[nb][1] = Vw[cr*36 + kw + tig + 4];
            }
#pragma unroll
            for (int nb = 0; nb < 8; nb++)
                mma_f16(oac[nb], af, bf[nb]);
        }
        __syncwarp();
    }

    const int bb = bh / H_, hh = bh % H_;
    const float inv0 = 1.f / lse[0], inv1 = 1.f / lse[1];
    const int t0 = q0 + m0w + gid;
#pragma unroll
    for (int nb = 0; nb < 8; nb++) {
        int col = hh*64 + nb*8 + tig*2;
        size_t oi0 = ((size_t)bb*T_ + t0    )*D_ + col;
        size_t oi1 = ((size_t)bb*T_ + t0 + 8)*D_ + col;
        *(__half2*)(o + oi0) = __floats2half2_rn(oac[nb][0]*inv0,
                                                 oac[nb][1]*inv0);
        *(__half2*)(o + oi1) = __floats2half2_rn(oac[nb][2]*inv1,
                                                 oac[nb][3]*inv1);
    }
}

// ---------------- launch ----------------------------------------------------
extern "C" void kernel_launch(void* const* d_in, const int* in_sizes, int n_in,
                              void* d_out, int out_size) {
    const int*   idx   = (const int*)  d_in[0];
    const float* tok   = (const float*)d_in[1];
    const float* pos   = (const float*)d_in[2];
    const float* Wq    = (const float*)d_in[3];
    const float* Wk    = (const float*)d_in[4];
    const float* Wv    = (const float*)d_in[5];
    const float* Wproj = (const float*)d_in[6];
    const float* bproj = (const float*)d_in[7];
    const float* ln1g  = (const float*)d_in[8];
    const float* ln1b  = (const float*)d_in[9];
    const float* ln2g  = (const float*)d_in[10];
    const float* ln2b  = (const float*)d_in[11];
    const float* W1    = (const float*)d_in[12];
    const float* b1    = (const float*)d_in[13];
    const float* W2    = (const float*)d_in[14];
    const float* b2    = (const float*)d_in[15];
    const float* lnfg  = (const float*)d_in[16];
    const float* lnfb  = (const float*)d_in[17];
    const float* Wlm   = (const float*)d_in[18];
    const float* blm   = (const float*)d_in[19];
    float* out = (float*)d_out;

    float *x;
    __half *xn, *q, *k, *v, *o, *h, *w;
    cudaGetSymbolAddress((void**)&x,  g_x);
    cudaGetSymbolAddress((void**)&xn, g_xn);
    cudaGetSymbolAddress((void**)&q,  g_q);
    cudaGetSymbolAddress((void**)&k,  g_k);
    cudaGetSymbolAddress((void**)&v,  g_v);
    cudaGetSymbolAddress((void**)&o,  g_o);
    cudaGetSymbolAddress((void**)&h,  g_h);
    cudaGetSymbolAddress((void**)&w,  g_w);

    cudaFuncSetAttribute(attn_h,
        cudaFuncAttributeMaxDynamicSharedMemorySize, ATT_SMEM);
    cudaFuncSetAttribute(gemm8<0,true>,
        cudaFuncAttributeMaxDynamicSharedMemorySize, GEMM_SMEM);
    cudaFuncSetAttribute(gemm8<1,false>,
        cudaFuncAttributeMaxDynamicSharedMemorySize, GEMM_SMEM);
    cudaFuncSetAttribute(gemm8<2,false>,
        cudaFuncAttributeMaxDynamicSharedMemorySize, GEMM_SMEM);
    cudaFuncSetAttribute(gemm8<3,false>,
        cudaFuncAttributeMaxDynamicSharedMemorySize, GEMM_SMEM);

    // weight pre-pack (transposed, fp16)
    {
        dim3 blk(32, 8);
        pack_qkv_h_kernel<<<dim3(D_/32, HS_/32, L_*H_), blk>>>(Wq, w+WQKV_OFF, 0);
        pack_qkv_h_kernel<<<dim3(D_/32, HS_/32, L_*H_), blk>>>(Wk, w+WQKV_OFF, 1);
        pack_qkv_h_kernel<<<dim3(D_/32, HS_/32, L_*H_), blk>>>(Wv, w+WQKV_OFF, 2);
        transpose_h_kernel<<<dim3(D_/32,  D_/32,  L_), blk>>>(Wproj, w+WPROJ_OFF, D_,  D_);
        transpose_h_kernel<<<dim3(D_/32,  FF_/32, L_), blk>>>(W1,    w+W1_OFF,    D_,  FF_);
        transpose_h_kernel<<<dim3(FF_/32, D_/32,  L_), blk>>>(W2,    w+W2_OFF,    FF_, D_);
        transpose_h_kernel<<<dim3(D_/32,  V_/32,  1 ), blk>>>(Wlm,   w+WLM_OFF,   D_,  V_);
    }

    embed_kernel<<<(N_*D_/4)/256, 256>>>(idx, tok, pos, x);

    for (int l = 0; l < L_; l++) {
        ln_kernel<<<N_/8, 256>>>(x, ln1g + l*D_, ln1b + l*D_, xn);

        gemm8<0,true><<<dim3(9, N_/128), 256, GEMM_SMEM>>>(
            xn, w + WQKV_OFF + (size_t)l*D_*3*D_, nullptr, nullptr,
            q, k, v, D_, 3*D_);

        attn_h<<<dim3(T_/64, B_*H_), 128, ATT_SMEM>>>(q, k, v, o);

        gemm8<3,false><<<dim3(3, N_/128), 256, GEMM_SMEM>>>(
            o, w + WPROJ_OFF + (size_t)l*D_*D_, bproj + l*D_, x,
            x, nullptr, nullptr, D_, D_);

        ln_kernel<<<N_/8, 256>>>(x, ln2g + l*D_, ln2b + l*D_, xn);

        gemm8<2,false><<<dim3(12, N_/128), 256, GEMM_SMEM>>>(
            xn, w + W1_OFF + (size_t)l*D_*FF_, b1 + l*FF_, nullptr,
            h, nullptr, nullptr, D_, FF_);

        gemm8<3,false><<<dim3(3, N_/128), 256, GEMM_SMEM>>>(
            h, w + W2_OFF + (size_t)l*FF_*D_, b2 + l*D_, x,
            x, nullptr, nullptr, FF_, D_);
    }

    ln_kernel<<<N_/8, 256>>>(x, lnfg, lnfb, xn);
    gemm8<1,false><<<dim3(1, N_/128), 256, GEMM_SMEM>>>(
        xn, w + WLM_OFF, blm, nullptr, out, nullptr, nullptr, D_, V_);
}